// round 6
// baseline (speedup 1.0000x reference)
#include <cuda_runtime.h>
#include <cuda_bf16.h>
#include <cstdint>

#define NTOK 8192      // B*S
#define CCH  128       // C
#define HID  256       // 2C
#define SEQ  4096      // S per batch
#define NH   4
#define HD   32

typedef unsigned int u32;

// ---------------- scratch (static device memory, no allocs) ----------------
__device__ float g_qp [NTOK * CCH];
__device__ float g_vp [NTOK * CCH];
__device__ float g_x  [NTOK * CCH];
__device__ float g_rs1[NTOK * CCH];
__device__ float g_h  [NTOK * HID];
// head-major split-bf16 operands: [b*NH+h][key][16 u32] (32 bf16 pairs packed)
__device__ u32 g_qhi[2 * NH * SEQ * 16];
__device__ u32 g_qlo[2 * NH * SEQ * 16];
__device__ u32 g_khi[2 * NH * SEQ * 16];
__device__ u32 g_klo[2 * NH * SEQ * 16];
__device__ u32 g_vrn[2 * NH * SEQ * 16];

// ---------------- bf16 pack helpers -----------------------------------------
__device__ __forceinline__ u32 packbf_tr(float x, float y) {   // truncation hi
    return (__float_as_uint(y) & 0xffff0000u) | (__float_as_uint(x) >> 16);
}
__device__ __forceinline__ float trhi(float x) {
    return __uint_as_float(__float_as_uint(x) & 0xffff0000u);
}
__device__ __forceinline__ u32 packbf_rn(float x, float y) {   // x->low, y->high
    u32 d; asm("cvt.rn.bf16x2.f32 %0,%2,%1;" : "=r"(d) : "f"(x), "f"(y)); return d;
}
__device__ __forceinline__ float exf(float x) {                // MUFU exp2
    float r; asm("ex2.approx.f32 %0,%1;" : "=f"(r) : "f"(x)); return r;
}
__device__ __forceinline__ u32 sptr(const void* p) {
    u32 a; asm("{.reg .u64 t; cvta.to.shared.u64 t,%1; cvt.u32.u64 %0,t;}" : "=r"(a) : "l"(p));
    return a;
}

// ---------------- mma / ldmatrix wrappers -----------------------------------
__device__ __forceinline__ void mma16816(float* c, const u32* a, const u32* b) {
    asm volatile(
        "mma.sync.aligned.m16n8k16.row.col.f32.bf16.bf16.f32 "
        "{%0,%1,%2,%3},{%4,%5,%6,%7},{%8,%9},{%0,%1,%2,%3};"
        : "+f"(c[0]), "+f"(c[1]), "+f"(c[2]), "+f"(c[3])
        : "r"(a[0]), "r"(a[1]), "r"(a[2]), "r"(a[3]), "r"(b[0]), "r"(b[1]));
}
__device__ __forceinline__ void ldsm4(u32& r0, u32& r1, u32& r2, u32& r3, u32 addr) {
    asm volatile("ldmatrix.sync.aligned.m8n8.x4.shared.b16 {%0,%1,%2,%3},[%4];"
                 : "=r"(r0), "=r"(r1), "=r"(r2), "=r"(r3) : "r"(addr));
}
__device__ __forceinline__ void ldsm4t(u32& r0, u32& r1, u32& r2, u32& r3, u32 addr) {
    asm volatile("ldmatrix.sync.aligned.m8n8.x4.trans.shared.b16 {%0,%1,%2,%3},[%4];"
                 : "=r"(r0), "=r"(r1), "=r"(r2), "=r"(r3) : "r"(addr));
}

// ---------------- LayerNorm + [B,C,S] -> [B*S, C] transpose ----------------
__global__ __launch_bounds__(256) void ln_transpose_kernel(
    const float* __restrict__ x, const float* __restrict__ gam,
    const float* __restrict__ bet, float* __restrict__ y)
{
    __shared__ float tile[CCH][17];
    const int tid = threadIdx.x;
    const int s0  = blockIdx.x * 16;
    const int bb  = blockIdx.y;

    #pragma unroll
    for (int it = 0; it < 8; it++) {
        int idx = tid + it * 256;
        int c = idx >> 4, t = idx & 15;
        tile[c][t] = x[(size_t)bb * CCH * SEQ + (size_t)c * SEQ + s0 + t];
    }
    __syncthreads();

    const int w = tid >> 5, lane = tid & 31;
    #pragma unroll
    for (int rep = 0; rep < 2; rep++) {
        int t = w * 2 + rep;
        float sum = 0.f, sq = 0.f;
        #pragma unroll
        for (int j = 0; j < 4; j++) {
            float v = tile[lane + 32 * j][t];
            sum += v; sq += v * v;
        }
        #pragma unroll
        for (int off = 16; off > 0; off >>= 1) {
            sum += __shfl_xor_sync(0xffffffffu, sum, off);
            sq  += __shfl_xor_sync(0xffffffffu, sq,  off);
        }
        float mu   = sum * (1.0f / CCH);
        float var  = sq * (1.0f / CCH) - mu * mu;
        float rstd = rsqrtf(var + 1e-5f);
        size_t row = ((size_t)bb * SEQ + s0 + t) * CCH;
        #pragma unroll
        for (int j = 0; j < 4; j++) {
            int c = lane + 32 * j;
            y[row + c] = (tile[c][t] - mu) * rstd * gam[c] + bet[c];
        }
    }
}

// ---------------- split-bf16 tensor-core GEMM --------------------------------
// MODE 0: fp32 C out.  MODE 1: split hi/lo u32 out (head-major, scaled).
// MODE 2: fp32 C out + RN bf16 u32 out (head-major).
#define AROW 12
#define BROW 36

template <bool LEAKY, bool RES, int MODE>
__global__ __launch_bounds__(128) void gemm_bf16_kernel(
    const float* __restrict__ A, const float* __restrict__ B,
    const float* __restrict__ bias, const float* __restrict__ res,
    float* __restrict__ C, u32* __restrict__ ohi, u32* __restrict__ olo,
    float scale, int N, int K, int M)
{
    __shared__ __align__(16) u32 sAhi[2][128 * AROW];
    __shared__ __align__(16) u32 sAlo[2][128 * AROW];
    __shared__ __align__(16) u32 sBhi[2][16 * BROW];
    __shared__ __align__(16) u32 sBlo[2][16 * BROW];

    const int tid  = threadIdx.x;
    const int lane = tid & 31;
    const int w    = tid >> 5;
    const int n0 = blockIdx.y * 128;
    const int m0 = blockIdx.x * 64;

    const int g  = lane >> 3;
    const int lr = lane & 7;

    int arow[4], acol[4];
    #pragma unroll
    for (int j = 0; j < 4; j++) {
        int idx = tid + 128 * j;
        arow[j] = idx >> 2;
        acol[j] = idx & 3;
    }
    int brow[2], bcol[2];
    #pragma unroll
    for (int j = 0; j < 2; j++) {
        int idx = tid + 128 * j;
        brow[j] = idx >> 4;
        bcol[j] = idx & 15;
    }

    float c[2][8][4];
    #pragma unroll
    for (int mi = 0; mi < 2; mi++)
        #pragma unroll
        for (int nt = 0; nt < 8; nt++)
            #pragma unroll
            for (int e = 0; e < 4; e++) c[mi][nt][e] = 0.f;

    const u32 bA0 = sptr(&sAhi[0][0]);
    const u32 bAl0 = sptr(&sAlo[0][0]);
    const u32 bB0 = sptr(&sBhi[0][0]);
    const u32 bBl0 = sptr(&sBlo[0][0]);
    const u32 abuf = 128 * AROW * 4;
    const u32 bbuf = 16 * BROW * 4;

    const int NT = K >> 4;

    float4 af[4], bf4[2];
    #pragma unroll
    for (int j = 0; j < 4; j++)
        af[j] = *reinterpret_cast<const float4*>(&A[(size_t)(n0 + arow[j]) * K + acol[j] * 4]);
    #pragma unroll
    for (int j = 0; j < 2; j++)
        bf4[j] = *reinterpret_cast<const float4*>(&B[(size_t)brow[j] * M + m0 + bcol[j] * 4]);

    #pragma unroll
    for (int j = 0; j < 4; j++) {
        int o = arow[j] * AROW + acol[j] * 2;
        float4 f = af[j];
        sAhi[0][o]     = packbf_tr(f.x, f.y);
        sAhi[0][o + 1] = packbf_tr(f.z, f.w);
        sAlo[0][o]     = packbf_rn(f.x - trhi(f.x), f.y - trhi(f.y));
        sAlo[0][o + 1] = packbf_rn(f.z - trhi(f.z), f.w - trhi(f.w));
    }
    #pragma unroll
    for (int j = 0; j < 2; j++) {
        int o = brow[j] * BROW + bcol[j] * 2;
        float4 f = bf4[j];
        sBhi[0][o]     = packbf_tr(f.x, f.y);
        sBhi[0][o + 1] = packbf_tr(f.z, f.w);
        sBlo[0][o]     = packbf_rn(f.x - trhi(f.x), f.y - trhi(f.y));
        sBlo[0][o + 1] = packbf_rn(f.z - trhi(f.z), f.w - trhi(f.w));
    }
    __syncthreads();

    for (int t = 0; t < NT; t++) {
        const int buf = t & 1;
        const u32 aH = bA0  + buf * abuf;
        const u32 aL = bAl0 + buf * abuf;
        const u32 bH = bB0  + buf * bbuf;
        const u32 bL = bBl0 + buf * bbuf;

        if (t + 1 < NT) {
            int k0 = (t + 1) * 16;
            #pragma unroll
            for (int j = 0; j < 4; j++)
                af[j] = *reinterpret_cast<const float4*>(&A[(size_t)(n0 + arow[j]) * K + k0 + acol[j] * 4]);
            #pragma unroll
            for (int j = 0; j < 2; j++)
                bf4[j] = *reinterpret_cast<const float4*>(&B[(size_t)(k0 + brow[j]) * M + m0 + bcol[j] * 4]);
        }

        u32 ahi[2][4], alo[2][4];
        #pragma unroll
        for (int mi = 0; mi < 2; mi++) {
            u32 off = (u32)((w * 32 + mi * 16 + (g & 1) * 8 + lr) * 48 + (g >> 1) * 16);
            ldsm4(ahi[mi][0], ahi[mi][1], ahi[mi][2], ahi[mi][3], aH + off);
            ldsm4(alo[mi][0], alo[mi][1], alo[mi][2], alo[mi][3], aL + off);
        }
        u32 bhi[8][2], blo[8][2];
        #pragma unroll
        for (int dp = 0; dp < 4; dp++) {
            u32 off = (u32)((8 * (g & 1) + lr) * 144 + (dp * 16 + 8 * (g >> 1)) * 2);
            ldsm4t(bhi[2 * dp][0], bhi[2 * dp][1], bhi[2 * dp + 1][0], bhi[2 * dp + 1][1], bH + off);
            ldsm4t(blo[2 * dp][0], blo[2 * dp][1], blo[2 * dp + 1][0], blo[2 * dp + 1][1], bL + off);
        }

        #pragma unroll
        for (int mi = 0; mi < 2; mi++)
            #pragma unroll
            for (int nt = 0; nt < 8; nt++) {
                mma16816(c[mi][nt], ahi[mi], bhi[nt]);
                mma16816(c[mi][nt], ahi[mi], blo[nt]);
                mma16816(c[mi][nt], alo[mi], bhi[nt]);
            }

        if (t + 1 < NT) {
            const int nb = (t + 1) & 1;
            #pragma unroll
            for (int j = 0; j < 4; j++) {
                int o = arow[j] * AROW + acol[j] * 2;
                float4 f = af[j];
                sAhi[nb][o]     = packbf_tr(f.x, f.y);
                sAhi[nb][o + 1] = packbf_tr(f.z, f.w);
                sAlo[nb][o]     = packbf_rn(f.x - trhi(f.x), f.y - trhi(f.y));
                sAlo[nb][o + 1] = packbf_rn(f.z - trhi(f.z), f.w - trhi(f.w));
            }
            #pragma unroll
            for (int j = 0; j < 2; j++) {
                int o = brow[j] * BROW + bcol[j] * 2;
                float4 f = bf4[j];
                sBhi[nb][o]     = packbf_tr(f.x, f.y);
                sBhi[nb][o + 1] = packbf_tr(f.z, f.w);
                sBlo[nb][o]     = packbf_rn(f.x - trhi(f.x), f.y - trhi(f.y));
                sBlo[nb][o + 1] = packbf_rn(f.z - trhi(f.z), f.w - trhi(f.w));
            }
        }
        __syncthreads();
    }

    // ---- epilogue -----------------------------------------------------------
    #pragma unroll
    for (int mi = 0; mi < 2; mi++) {
        int r0 = n0 + w * 32 + mi * 16 + (lane >> 2);
        #pragma unroll
        for (int nt = 0; nt < 8; nt++) {
            int col = m0 + nt * 8 + (lane & 3) * 2;
            float2 bb = *reinterpret_cast<const float2*>(&bias[col]);
            float v0 = c[mi][nt][0] + bb.x;
            float v1 = c[mi][nt][1] + bb.y;
            float v2 = c[mi][nt][2] + bb.x;
            float v3 = c[mi][nt][3] + bb.y;
            if (LEAKY) {
                v0 = fmaxf(v0, 0.f) + 0.01f * fminf(v0, 0.f);
                v1 = fmaxf(v1, 0.f) + 0.01f * fminf(v1, 0.f);
                v2 = fmaxf(v2, 0.f) + 0.01f * fminf(v2, 0.f);
                v3 = fmaxf(v3, 0.f) + 0.01f * fminf(v3, 0.f);
            }
            if (RES) {
                float2 r4a = *reinterpret_cast<const float2*>(&res[(size_t)r0 * M + col]);
                float2 r4b = *reinterpret_cast<const float2*>(&res[(size_t)(r0 + 8) * M + col]);
                v0 += r4a.x; v1 += r4a.y; v2 += r4b.x; v3 += r4b.y;
            }
            if (MODE == 0 || MODE == 2) {
                *reinterpret_cast<float2*>(&C[(size_t)r0 * M + col])       = make_float2(v0, v1);
                *reinterpret_cast<float2*>(&C[(size_t)(r0 + 8) * M + col]) = make_float2(v2, v3);
            }
            if (MODE == 1 || MODE == 2) {
                int h = col >> 5, dpair = (col & 31) >> 1;
                int b0_ = r0 >> 12, s0_ = r0 & (SEQ - 1);
                size_t oA = ((size_t)(b0_ * NH + h) * SEQ + s0_) * 16 + dpair;
                size_t oB = oA + 8 * 16;     // row r0+8 (same b,h since r0%16<8)
                if (MODE == 1) {
                    float w0 = v0 * scale, w1 = v1 * scale;
                    float w2 = v2 * scale, w3 = v3 * scale;
                    ohi[oA] = packbf_tr(w0, w1);
                    ohi[oB] = packbf_tr(w2, w3);
                    olo[oA] = packbf_rn(w0 - trhi(w0), w1 - trhi(w1));
                    olo[oB] = packbf_rn(w2 - trhi(w2), w3 - trhi(w3));
                } else {
                    ohi[oA] = packbf_rn(v0, v1);
                    ohi[oB] = packbf_rn(v2, v3);
                }
            }
        }
    }
}

// ---------------- FA2 attention on tensor cores (pre-split operands) --------
#define KVT 64
#define ROWU 20   // smem row stride in u32 (80B padded)

__global__ __launch_bounds__(128, 2) void attn_kernel(float* __restrict__ xo)
{
    __shared__ __align__(16) u32 skhi[2][KVT * ROWU];
    __shared__ __align__(16) u32 sklo[2][KVT * ROWU];
    __shared__ __align__(16) u32 svv [2][KVT * ROWU];

    const int tid  = threadIdx.x;
    const int lane = tid & 31;
    const int w    = tid >> 5;
    const int bh   = blockIdx.y;           // b*NH + h
    const int bb   = bh >> 2, h = bh & 3;
    const int sq0  = blockIdx.x * 128 + w * 32;   // local q row base for warp

    // ---- load Q fragments (already split + scaled) -------------------------
    u32 qhiR[2][2][4], qloR[2][2][4];
    #pragma unroll
    for (int mi = 0; mi < 2; mi++) {
        size_t qb = ((size_t)bh * SEQ + sq0 + mi * 16 + (lane >> 2)) * 16;
        #pragma unroll
        for (int kt = 0; kt < 2; kt++) {
            int d0 = kt * 8 + (lane & 3);
            qhiR[mi][kt][0] = g_qhi[qb + d0];
            qhiR[mi][kt][1] = g_qhi[qb + 8 * 16 + d0];
            qhiR[mi][kt][2] = g_qhi[qb + d0 + 4];
            qhiR[mi][kt][3] = g_qhi[qb + 8 * 16 + d0 + 4];
            qloR[mi][kt][0] = g_qlo[qb + d0];
            qloR[mi][kt][1] = g_qlo[qb + 8 * 16 + d0];
            qloR[mi][kt][2] = g_qlo[qb + d0 + 4];
            qloR[mi][kt][3] = g_qlo[qb + 8 * 16 + d0 + 4];
        }
    }

    float o[2][4][4];
    #pragma unroll
    for (int mi = 0; mi < 2; mi++)
        #pragma unroll
        for (int dn = 0; dn < 4; dn++)
            #pragma unroll
            for (int e = 0; e < 4; e++) o[mi][dn][e] = 0.f;
    float mrow[2][2] = {{-1e30f, -1e30f}, {-1e30f, -1e30f}};
    float lrow[2][2] = {{0.f, 0.f}, {0.f, 0.f}};

    // staging: 2 uint4 per array per thread
    int srow[2], scq[2];
    #pragma unroll
    for (int j = 0; j < 2; j++) {
        int idx = tid + 128 * j;
        srow[j] = idx >> 2;
        scq[j]  = idx & 3;
    }
    const size_t kvbase = (size_t)bh * SEQ * 16;

    const int g  = lane >> 3;
    const int lr = lane & 7;
    const u32 bKhi0 = sptr(&skhi[0][0]);
    const u32 bKlo0 = sptr(&sklo[0][0]);
    const u32 bV0   = sptr(&svv[0][0]);
    const u32 bufstride = KVT * ROWU * 4;

    // prefetch tile 0
    uint4 pk[2], pl[2], pv[2];
    #pragma unroll
    for (int j = 0; j < 2; j++) {
        size_t go = kvbase + (size_t)srow[j] * 16 + scq[j] * 4;
        pk[j] = *reinterpret_cast<const uint4*>(g_khi + go);
        pl[j] = *reinterpret_cast<const uint4*>(g_klo + go);
        pv[j] = *reinterpret_cast<const uint4*>(g_vrn + go);
    }
    #pragma unroll
    for (int j = 0; j < 2; j++) {
        u32 so = srow[j] * ROWU + scq[j] * 4;
        *reinterpret_cast<uint4*>(&skhi[0][so]) = pk[j];
        *reinterpret_cast<uint4*>(&sklo[0][so]) = pl[j];
        *reinterpret_cast<uint4*>(&svv [0][so]) = pv[j];
    }
    __syncthreads();

    const int NT = SEQ / KVT;
    for (int t = 0; t < NT; t++) {
        const int buf = t & 1;
        const u32 bKhi = bKhi0 + buf * bufstride;
        const u32 bKlo = bKlo0 + buf * bufstride;
        const u32 bV   = bV0   + buf * bufstride;

        if (t + 1 < NT) {
            #pragma unroll
            for (int j = 0; j < 2; j++) {
                size_t go = kvbase + (size_t)((t + 1) * KVT + srow[j]) * 16 + scq[j] * 4;
                pk[j] = *reinterpret_cast<const uint4*>(g_khi + go);
                pl[j] = *reinterpret_cast<const uint4*>(g_klo + go);
                pv[j] = *reinterpret_cast<const uint4*>(g_vrn + go);
            }
        }

        float s[2][8][4];
        #pragma unroll
        for (int mi = 0; mi < 2; mi++)
            #pragma unroll
            for (int nt = 0; nt < 8; nt++)
                #pragma unroll
                for (int e = 0; e < 4; e++) s[mi][nt][e] = 0.f;

        #pragma unroll
        for (int kt = 0; kt < 2; kt++) {
            u32 bh_[8][2], bl_[8][2];
            #pragma unroll
            for (int ap = 0; ap < 4; ap++) {
                u32 off = (u32)((16 * ap + 8 * (g >> 1) + lr) * 80 + (kt * 16 + 8 * (g & 1)) * 2);
                ldsm4(bh_[2 * ap][0], bh_[2 * ap][1], bh_[2 * ap + 1][0], bh_[2 * ap + 1][1], bKhi + off);
                ldsm4(bl_[2 * ap][0], bl_[2 * ap][1], bl_[2 * ap + 1][0], bl_[2 * ap + 1][1], bKlo + off);
            }
            #pragma unroll
            for (int mi = 0; mi < 2; mi++)
                #pragma unroll
                for (int nt = 0; nt < 8; nt++) {
                    mma16816(s[mi][nt], qhiR[mi][kt], bh_[nt]);
                    mma16816(s[mi][nt], qloR[mi][kt], bh_[nt]);
                    mma16816(s[mi][nt], qhiR[mi][kt], bl_[nt]);
                }
        }

        #pragma unroll
        for (int mi = 0; mi < 2; mi++) {
            float mx0 = -1e30f, mx1 = -1e30f;
            #pragma unroll
            for (int nt = 0; nt < 8; nt++) {
                mx0 = fmaxf(mx0, fmaxf(s[mi][nt][0], s[mi][nt][1]));
                mx1 = fmaxf(mx1, fmaxf(s[mi][nt][2], s[mi][nt][3]));
            }
            mx0 = fmaxf(mx0, __shfl_xor_sync(0xffffffffu, mx0, 1));
            mx0 = fmaxf(mx0, __shfl_xor_sync(0xffffffffu, mx0, 2));
            mx1 = fmaxf(mx1, __shfl_xor_sync(0xffffffffu, mx1, 1));
            mx1 = fmaxf(mx1, __shfl_xor_sync(0xffffffffu, mx1, 2));
            float mn0 = fmaxf(mrow[mi][0], mx0);
            float mn1 = fmaxf(mrow[mi][1], mx1);
            float al0 = exf(mrow[mi][0] - mn0);
            float al1 = exf(mrow[mi][1] - mn1);
            float sum0 = 0.f, sum1 = 0.f;
            #pragma unroll
            for (int nt = 0; nt < 8; nt++) {
                float p0 = exf(s[mi][nt][0] - mn0);
                float p1 = exf(s[mi][nt][1] - mn0);
                float p2 = exf(s[mi][nt][2] - mn1);
                float p3 = exf(s[mi][nt][3] - mn1);
                s[mi][nt][0] = p0; s[mi][nt][1] = p1;
                s[mi][nt][2] = p2; s[mi][nt][3] = p3;
                sum0 += p0 + p1; sum1 += p2 + p3;
            }
            sum0 += __shfl_xor_sync(0xffffffffu, sum0, 1);
            sum0 += __shfl_xor_sync(0xffffffffu, sum0, 2);
            sum1 += __shfl_xor_sync(0xffffffffu, sum1, 1);
            sum1 += __shfl_xor_sync(0xffffffffu, sum1, 2);
            lrow[mi][0] = lrow[mi][0] * al0 + sum0;
            lrow[mi][1] = lrow[mi][1] * al1 + sum1;
            mrow[mi][0] = mn0; mrow[mi][1] = mn1;
            #pragma unroll
            for (int dn = 0; dn < 4; dn++) {
                o[mi][dn][0] *= al0; o[mi][dn][1] *= al0;
                o[mi][dn][2] *= al1; o[mi][dn][3] *= al1;
            }
        }

        #pragma unroll
        for (int kt = 0; kt < 4; kt++) {
            u32 bv[4][2];
            #pragma unroll
            for (int dp = 0; dp < 2; dp++) {
                u32 off = (u32)((16 * kt + 8 * (g & 1) + lr) * 80 + (dp * 16 + 8 * (g >> 1)) * 2);
                ldsm4t(bv[2 * dp][0], bv[2 * dp][1], bv[2 * dp + 1][0], bv[2 * dp + 1][1], bV + off);
            }
            #pragma unroll
            for (int mi = 0; mi < 2; mi++) {
                u32 pa[4];
                pa[0] = packbf_rn(s[mi][2 * kt][0],     s[mi][2 * kt][1]);
                pa[1] = packbf_rn(s[mi][2 * kt][2],     s[mi][2 * kt][3]);
                pa[2] = packbf_rn(s[mi][2 * kt + 1][0], s[mi][2 * kt + 1][1]);
                pa[3] = packbf_rn(s[mi][2 * kt + 1][2], s[mi][2 * kt + 1][3]);
                #pragma unroll
                for (int dn = 0; dn < 4; dn++)
                    mma16816(o[mi][dn], pa, bv[dn]);
            }
        }

        if (t + 1 < NT) {
            const int nb = (t + 1) & 1;
            #pragma unroll
            for (int j = 0; j < 2; j++) {
                u32 so = srow[j] * ROWU + scq[j] * 4;
                *reinterpret_cast<uint4*>(&skhi[nb][so]) = pk[j];
                *reinterpret_cast<uint4*>(&sklo[nb][so]) = pl[j];
                *reinterpret_cast<uint4*>(&svv [nb][so]) = pv[j];
            }
        }
        __syncthreads();
    }

    // ---- finalize & write ----------------------------------------------------
    #pragma unroll
    for (int mi = 0; mi < 2; mi++) {
        float inv0 = 1.0f / lrow[mi][0];
        float inv1 = 1.0f / lrow[mi][1];
        int r = bb * SEQ + sq0 + mi * 16 + (lane >> 2);
        #pragma unroll
        for (int dn = 0; dn < 4; dn++) {
            int cc = h * HD + dn * 8 + 2 * (lane & 3);
            float2 o0 = {o[mi][dn][0] * inv0, o[mi][dn][1] * inv0};
            float2 o1 = {o[mi][dn][2] * inv1, o[mi][dn][3] * inv1};
            *reinterpret_cast<float2*>(xo + (size_t)r * CCH + cc)       = o0;
            *reinterpret_cast<float2*>(xo + (size_t)(r + 8) * CCH + cc) = o1;
        }
    }
}

// ---------------- [B*S, C] -> [B, C, S] output transpose -------------------
__global__ __launch_bounds__(256) void out_transpose_kernel(
    const float* __restrict__ src, float* __restrict__ dst)
{
    __shared__ float t[32][33];
    const int tx = threadIdx.x, ty = threadIdx.y;
    const int s0 = blockIdx.x * 32;
    const int c0 = blockIdx.y * 32;
    const int bb = blockIdx.z;
    #pragma unroll
    for (int i = ty; i < 32; i += 8)
        t[i][tx] = src[((size_t)bb * SEQ + s0 + i) * CCH + c0 + tx];
    __syncthreads();
    #pragma unroll
    for (int i = ty; i < 32; i += 8)
        dst[(size_t)bb * CCH * SEQ + (size_t)(c0 + i) * SEQ + s0 + tx] = t[tx][i];
}

// ---------------- launch ----------------------------------------------------
static float* symf(const void* symbol) {
    void* p = nullptr;
    cudaGetSymbolAddress(&p, symbol);
    return reinterpret_cast<float*>(p);
}
static u32* symu(const void* symbol) {
    void* p = nullptr;
    cudaGetSymbolAddress(&p, symbol);
    return reinterpret_cast<u32*>(p);
}

extern "C" void kernel_launch(void* const* d_in, const int* in_sizes, int n_in,
                              void* d_out, int out_size)
{
    const float* q = (const float*)d_in[0];
    const float* k = (const float*)d_in[1];
    const float* v = (const float*)d_in[2];
    const float* ln_g[3]  = {(const float*)d_in[3],  (const float*)d_in[9],  (const float*)d_in[15]};
    const float* ln_b[3]  = {(const float*)d_in[4],  (const float*)d_in[10], (const float*)d_in[16]};
    const float* w1[3]    = {(const float*)d_in[5],  (const float*)d_in[11], (const float*)d_in[17]};
    const float* b1[3]    = {(const float*)d_in[6],  (const float*)d_in[12], (const float*)d_in[18]};
    const float* w2[3]    = {(const float*)d_in[7],  (const float*)d_in[13], (const float*)d_in[19]};
    const float* b2[3]    = {(const float*)d_in[8],  (const float*)d_in[14], (const float*)d_in[20]};
    const float* m1_w1 = (const float*)d_in[21];
    const float* m1_b1 = (const float*)d_in[22];
    const float* m1_w2 = (const float*)d_in[23];
    const float* m1_b2 = (const float*)d_in[24];
    const float* m2_w1 = (const float*)d_in[25];
    const float* m2_b1 = (const float*)d_in[26];
    const float* m2_w2 = (const float*)d_in[27];
    const float* m2_b2 = (const float*)d_in[28];

    float* qp  = symf(g_qp);
    float* vp  = symf(g_vp);
    float* x   = symf(g_x);
    float* rs1 = symf(g_rs1);
    float* hb  = symf(g_h);
    u32* qhi = symu(g_qhi);
    u32* qlo = symu(g_qlo);
    u32* khi = symu(g_khi);
    u32* klo = symu(g_klo);
    u32* vrn = symu(g_vrn);

    const float qsc = 1.44269504088896f / 5.65685424949238f;  // log2e/sqrt(32)

    dim3 g1(HID / 64, NTOK / 128);   // (4, 64)
    dim3 g2(CCH / 64, NTOK / 128);   // (2, 64)

    // q projection -> split bf16 (scaled)
    ln_transpose_kernel<<<dim3(SEQ / 16, 2), 256>>>(q, ln_g[0], ln_b[0], x);
    gemm_bf16_kernel<true,  false, 0><<<g1, 128>>>(x,  w1[0], b1[0], nullptr, hb, nullptr, nullptr, 0.f, NTOK, CCH, HID);
    gemm_bf16_kernel<false, false, 1><<<g2, 128>>>(hb, w2[0], b2[0], nullptr, nullptr, qhi, qlo, qsc, NTOK, HID, CCH);

    // k projection -> split bf16
    ln_transpose_kernel<<<dim3(SEQ / 16, 2), 256>>>(k, ln_g[1], ln_b[1], x);
    gemm_bf16_kernel<true,  false, 0><<<g1, 128>>>(x,  w1[1], b1[1], nullptr, hb, nullptr, nullptr, 0.f, NTOK, CCH, HID);
    gemm_bf16_kernel<false, false, 1><<<g2, 128>>>(hb, w2[1], b2[1], nullptr, nullptr, khi, klo, 1.f, NTOK, HID, CCH);

    // v projection -> fp32 (residual) + rn bf16 (PV)
    ln_transpose_kernel<<<dim3(SEQ / 16, 2), 256>>>(v, ln_g[2], ln_b[2], x);
    gemm_bf16_kernel<true,  false, 0><<<g1, 128>>>(x,  w1[2], b1[2], nullptr, hb, nullptr, nullptr, 0.f, NTOK, CCH, HID);
    gemm_bf16_kernel<false, false, 2><<<g2, 128>>>(hb, w2[2], b2[2], nullptr, vp, vrn, nullptr, 0.f, NTOK, HID, CCH);

    attn_kernel<<<dim3(SEQ / 128, 2 * NH), 128>>>(x);

    gemm_bf16_kernel<true,  false, 0><<<g1, 128>>>(x,   m1_w1, m1_b1, nullptr, hb,  nullptr, nullptr, 0.f, NTOK, CCH, HID);
    gemm_bf16_kernel<false, true,  0><<<g2, 128>>>(hb,  m1_w2, m1_b2, vp,      rs1, nullptr, nullptr, 0.f, NTOK, HID, CCH);
    gemm_bf16_kernel<true,  false, 0><<<g1, 128>>>(rs1, m2_w1, m2_b1, nullptr, hb,  nullptr, nullptr, 0.f, NTOK, CCH, HID);
    gemm_bf16_kernel<false, true,  0><<<g2, 128>>>(hb,  m2_w2, m2_b2, rs1,     qp,  nullptr, nullptr, 0.f, NTOK, HID, CCH);

    out_transpose_kernel<<<dim3(SEQ / 32, CCH / 32, 2), dim3(32, 8)>>>(qp, (float*)d_out);
}

// round 7
// speedup vs baseline: 1.2113x; 1.2113x over previous
#include <cuda_runtime.h>
#include <cuda_bf16.h>
#include <cstdint>

#define NTOK 8192      // B*S
#define CCH  128       // C
#define HID  256       // 2C
#define SEQ  4096      // S per batch
#define NH   4
#define HD   32

typedef unsigned int u32;

// ---------------- scratch (static device memory, no allocs) ----------------
__device__ float g_qp [NTOK * CCH];
__device__ float g_vp [NTOK * CCH];
__device__ float g_x  [NTOK * CCH];
__device__ float g_rs1[NTOK * CCH];
__device__ float g_h  [NTOK * HID];
// head-major fp16 operands: [b*NH+h][token][16 u32] (32 fp16 pairs packed)
__device__ u32 g_qf[2 * NH * SEQ * 16];
__device__ u32 g_kf[2 * NH * SEQ * 16];
__device__ u32 g_vf[2 * NH * SEQ * 16];

// ---------------- pack helpers ----------------------------------------------
__device__ __forceinline__ u32 packbf_tr(float x, float y) {   // truncation hi
    return (__float_as_uint(y) & 0xffff0000u) | (__float_as_uint(x) >> 16);
}
__device__ __forceinline__ float trhi(float x) {
    return __uint_as_float(__float_as_uint(x) & 0xffff0000u);
}
__device__ __forceinline__ u32 packbf_rn(float x, float y) {   // x->low, y->high
    u32 d; asm("cvt.rn.bf16x2.f32 %0,%2,%1;" : "=r"(d) : "f"(x), "f"(y)); return d;
}
__device__ __forceinline__ u32 packhf(float x, float y) {      // fp16x2, x->low
    u32 d; asm("cvt.rn.f16x2.f32 %0,%2,%1;" : "=r"(d) : "f"(x), "f"(y)); return d;
}
__device__ __forceinline__ float exf(float x) {                // MUFU exp2
    float r; asm("ex2.approx.f32 %0,%1;" : "=f"(r) : "f"(x)); return r;
}
__device__ __forceinline__ u32 sptr(const void* p) {
    u32 a; asm("{.reg .u64 t; cvta.to.shared.u64 t,%1; cvt.u32.u64 %0,t;}" : "=r"(a) : "l"(p));
    return a;
}

// ---------------- mma / ldmatrix wrappers -----------------------------------
__device__ __forceinline__ void mma16816(float* c, const u32* a, const u32* b) {  // bf16
    asm volatile(
        "mma.sync.aligned.m16n8k16.row.col.f32.bf16.bf16.f32 "
        "{%0,%1,%2,%3},{%4,%5,%6,%7},{%8,%9},{%0,%1,%2,%3};"
        : "+f"(c[0]), "+f"(c[1]), "+f"(c[2]), "+f"(c[3])
        : "r"(a[0]), "r"(a[1]), "r"(a[2]), "r"(a[3]), "r"(b[0]), "r"(b[1]));
}
__device__ __forceinline__ void mma16816h(float* c, const u32* a, const u32* b) { // fp16
    asm volatile(
        "mma.sync.aligned.m16n8k16.row.col.f32.f16.f16.f32 "
        "{%0,%1,%2,%3},{%4,%5,%6,%7},{%8,%9},{%0,%1,%2,%3};"
        : "+f"(c[0]), "+f"(c[1]), "+f"(c[2]), "+f"(c[3])
        : "r"(a[0]), "r"(a[1]), "r"(a[2]), "r"(a[3]), "r"(b[0]), "r"(b[1]));
}
__device__ __forceinline__ void ldsm4(u32& r0, u32& r1, u32& r2, u32& r3, u32 addr) {
    asm volatile("ldmatrix.sync.aligned.m8n8.x4.shared.b16 {%0,%1,%2,%3},[%4];"
                 : "=r"(r0), "=r"(r1), "=r"(r2), "=r"(r3) : "r"(addr));
}
__device__ __forceinline__ void ldsm4t(u32& r0, u32& r1, u32& r2, u32& r3, u32 addr) {
    asm volatile("ldmatrix.sync.aligned.m8n8.x4.trans.shared.b16 {%0,%1,%2,%3},[%4];"
                 : "=r"(r0), "=r"(r1), "=r"(r2), "=r"(r3) : "r"(addr));
}

// ---------------- LayerNorm + [B,C,S] -> [B*S, C] transpose ----------------
__global__ __launch_bounds__(256) void ln_transpose_kernel(
    const float* __restrict__ x, const float* __restrict__ gam,
    const float* __restrict__ bet, float* __restrict__ y)
{
    __shared__ float tile[CCH][17];
    const int tid = threadIdx.x;
    const int s0  = blockIdx.x * 16;
    const int bb  = blockIdx.y;

    #pragma unroll
    for (int it = 0; it < 8; it++) {
        int idx = tid + it * 256;
        int c = idx >> 4, t = idx & 15;
        tile[c][t] = x[(size_t)bb * CCH * SEQ + (size_t)c * SEQ + s0 + t];
    }
    __syncthreads();

    const int w = tid >> 5, lane = tid & 31;
    #pragma unroll
    for (int rep = 0; rep < 2; rep++) {
        int t = w * 2 + rep;
        float sum = 0.f, sq = 0.f;
        #pragma unroll
        for (int j = 0; j < 4; j++) {
            float v = tile[lane + 32 * j][t];
            sum += v; sq += v * v;
        }
        #pragma unroll
        for (int off = 16; off > 0; off >>= 1) {
            sum += __shfl_xor_sync(0xffffffffu, sum, off);
            sq  += __shfl_xor_sync(0xffffffffu, sq,  off);
        }
        float mu   = sum * (1.0f / CCH);
        float var  = sq * (1.0f / CCH) - mu * mu;
        float rstd = rsqrtf(var + 1e-5f);
        size_t row = ((size_t)bb * SEQ + s0 + t) * CCH;
        #pragma unroll
        for (int j = 0; j < 4; j++) {
            int c = lane + 32 * j;
            y[row + c] = (tile[c][t] - mu) * rstd * gam[c] + bet[c];
        }
    }
}

// ---------------- split-bf16 tensor-core GEMM --------------------------------
// MODE 0: fp32 C out.  MODE 1: fp16 u32 out (head-major, scaled).
// MODE 2: fp32 C out + fp16 u32 out (head-major).
#define AROW 12
#define BROW 36

template <bool LEAKY, bool RES, int MODE>
__global__ __launch_bounds__(128) void gemm_bf16_kernel(
    const float* __restrict__ A, const float* __restrict__ B,
    const float* __restrict__ bias, const float* __restrict__ res,
    float* __restrict__ C, u32* __restrict__ oh16,
    float scale, int N, int K, int M)
{
    __shared__ __align__(16) u32 sAhi[2][128 * AROW];
    __shared__ __align__(16) u32 sAlo[2][128 * AROW];
    __shared__ __align__(16) u32 sBhi[2][16 * BROW];
    __shared__ __align__(16) u32 sBlo[2][16 * BROW];

    const int tid  = threadIdx.x;
    const int lane = tid & 31;
    const int w    = tid >> 5;
    const int n0 = blockIdx.y * 128;
    const int m0 = blockIdx.x * 64;

    const int g  = lane >> 3;
    const int lr = lane & 7;

    int arow[4], acol[4];
    #pragma unroll
    for (int j = 0; j < 4; j++) {
        int idx = tid + 128 * j;
        arow[j] = idx >> 2;
        acol[j] = idx & 3;
    }
    int brow[2], bcol[2];
    #pragma unroll
    for (int j = 0; j < 2; j++) {
        int idx = tid + 128 * j;
        brow[j] = idx >> 4;
        bcol[j] = idx & 15;
    }

    float c[2][8][4];
    #pragma unroll
    for (int mi = 0; mi < 2; mi++)
        #pragma unroll
        for (int nt = 0; nt < 8; nt++)
            #pragma unroll
            for (int e = 0; e < 4; e++) c[mi][nt][e] = 0.f;

    const u32 bA0 = sptr(&sAhi[0][0]);
    const u32 bAl0 = sptr(&sAlo[0][0]);
    const u32 bB0 = sptr(&sBhi[0][0]);
    const u32 bBl0 = sptr(&sBlo[0][0]);
    const u32 abuf = 128 * AROW * 4;
    const u32 bbuf = 16 * BROW * 4;

    const int NT = K >> 4;

    float4 af[4], bf4[2];
    #pragma unroll
    for (int j = 0; j < 4; j++)
        af[j] = *reinterpret_cast<const float4*>(&A[(size_t)(n0 + arow[j]) * K + acol[j] * 4]);
    #pragma unroll
    for (int j = 0; j < 2; j++)
        bf4[j] = *reinterpret_cast<const float4*>(&B[(size_t)brow[j] * M + m0 + bcol[j] * 4]);

    #pragma unroll
    for (int j = 0; j < 4; j++) {
        int o = arow[j] * AROW + acol[j] * 2;
        float4 f = af[j];
        sAhi[0][o]     = packbf_tr(f.x, f.y);
        sAhi[0][o + 1] = packbf_tr(f.z, f.w);
        sAlo[0][o]     = packbf_rn(f.x - trhi(f.x), f.y - trhi(f.y));
        sAlo[0][o + 1] = packbf_rn(f.z - trhi(f.z), f.w - trhi(f.w));
    }
    #pragma unroll
    for (int j = 0; j < 2; j++) {
        int o = brow[j] * BROW + bcol[j] * 2;
        float4 f = bf4[j];
        sBhi[0][o]     = packbf_tr(f.x, f.y);
        sBhi[0][o + 1] = packbf_tr(f.z, f.w);
        sBlo[0][o]     = packbf_rn(f.x - trhi(f.x), f.y - trhi(f.y));
        sBlo[0][o + 1] = packbf_rn(f.z - trhi(f.z), f.w - trhi(f.w));
    }
    __syncthreads();

    for (int t = 0; t < NT; t++) {
        const int buf = t & 1;
        const u32 aH = bA0  + buf * abuf;
        const u32 aL = bAl0 + buf * abuf;
        const u32 bH = bB0  + buf * bbuf;
        const u32 bL = bBl0 + buf * bbuf;

        if (t + 1 < NT) {
            int k0 = (t + 1) * 16;
            #pragma unroll
            for (int j = 0; j < 4; j++)
                af[j] = *reinterpret_cast<const float4*>(&A[(size_t)(n0 + arow[j]) * K + k0 + acol[j] * 4]);
            #pragma unroll
            for (int j = 0; j < 2; j++)
                bf4[j] = *reinterpret_cast<const float4*>(&B[(size_t)(k0 + brow[j]) * M + m0 + bcol[j] * 4]);
        }

        u32 ahi[2][4], alo[2][4];
        #pragma unroll
        for (int mi = 0; mi < 2; mi++) {
            u32 off = (u32)((w * 32 + mi * 16 + (g & 1) * 8 + lr) * 48 + (g >> 1) * 16);
            ldsm4(ahi[mi][0], ahi[mi][1], ahi[mi][2], ahi[mi][3], aH + off);
            ldsm4(alo[mi][0], alo[mi][1], alo[mi][2], alo[mi][3], aL + off);
        }
        u32 bhi[8][2], blo[8][2];
        #pragma unroll
        for (int dp = 0; dp < 4; dp++) {
            u32 off = (u32)((8 * (g & 1) + lr) * 144 + (dp * 16 + 8 * (g >> 1)) * 2);
            ldsm4t(bhi[2 * dp][0], bhi[2 * dp][1], bhi[2 * dp + 1][0], bhi[2 * dp + 1][1], bH + off);
            ldsm4t(blo[2 * dp][0], blo[2 * dp][1], blo[2 * dp + 1][0], blo[2 * dp + 1][1], bL + off);
        }

        #pragma unroll
        for (int mi = 0; mi < 2; mi++)
            #pragma unroll
            for (int nt = 0; nt < 8; nt++) {
                mma16816(c[mi][nt], ahi[mi], bhi[nt]);
                mma16816(c[mi][nt], ahi[mi], blo[nt]);
                mma16816(c[mi][nt], alo[mi], bhi[nt]);
            }

        if (t + 1 < NT) {
            const int nb = (t + 1) & 1;
            #pragma unroll
            for (int j = 0; j < 4; j++) {
                int o = arow[j] * AROW + acol[j] * 2;
                float4 f = af[j];
                sAhi[nb][o]     = packbf_tr(f.x, f.y);
                sAhi[nb][o + 1] = packbf_tr(f.z, f.w);
                sAlo[nb][o]     = packbf_rn(f.x - trhi(f.x), f.y - trhi(f.y));
                sAlo[nb][o + 1] = packbf_rn(f.z - trhi(f.z), f.w - trhi(f.w));
            }
            #pragma unroll
            for (int j = 0; j < 2; j++) {
                int o = brow[j] * BROW + bcol[j] * 2;
                float4 f = bf4[j];
                sBhi[nb][o]     = packbf_tr(f.x, f.y);
                sBhi[nb][o + 1] = packbf_tr(f.z, f.w);
                sBlo[nb][o]     = packbf_rn(f.x - trhi(f.x), f.y - trhi(f.y));
                sBlo[nb][o + 1] = packbf_rn(f.z - trhi(f.z), f.w - trhi(f.w));
            }
        }
        __syncthreads();
    }

    // ---- epilogue -----------------------------------------------------------
    #pragma unroll
    for (int mi = 0; mi < 2; mi++) {
        int r0 = n0 + w * 32 + mi * 16 + (lane >> 2);
        #pragma unroll
        for (int nt = 0; nt < 8; nt++) {
            int col = m0 + nt * 8 + (lane & 3) * 2;
            float2 bb = *reinterpret_cast<const float2*>(&bias[col]);
            float v0 = c[mi][nt][0] + bb.x;
            float v1 = c[mi][nt][1] + bb.y;
            float v2 = c[mi][nt][2] + bb.x;
            float v3 = c[mi][nt][3] + bb.y;
            if (LEAKY) {
                v0 = fmaxf(v0, 0.f) + 0.01f * fminf(v0, 0.f);
                v1 = fmaxf(v1, 0.f) + 0.01f * fminf(v1, 0.f);
                v2 = fmaxf(v2, 0.f) + 0.01f * fminf(v2, 0.f);
                v3 = fmaxf(v3, 0.f) + 0.01f * fminf(v3, 0.f);
            }
            if (RES) {
                float2 r4a = *reinterpret_cast<const float2*>(&res[(size_t)r0 * M + col]);
                float2 r4b = *reinterpret_cast<const float2*>(&res[(size_t)(r0 + 8) * M + col]);
                v0 += r4a.x; v1 += r4a.y; v2 += r4b.x; v3 += r4b.y;
            }
            if (MODE == 0 || MODE == 2) {
                *reinterpret_cast<float2*>(&C[(size_t)r0 * M + col])       = make_float2(v0, v1);
                *reinterpret_cast<float2*>(&C[(size_t)(r0 + 8) * M + col]) = make_float2(v2, v3);
            }
            if (MODE == 1 || MODE == 2) {
                int h = col >> 5, dpair = (col & 31) >> 1;
                int b0_ = r0 >> 12, s0_ = r0 & (SEQ - 1);
                size_t oA = ((size_t)(b0_ * NH + h) * SEQ + s0_) * 16 + dpair;
                size_t oB = oA + 8 * 16;     // row r0+8 (same b,h)
                oh16[oA] = packhf(v0 * scale, v1 * scale);
                oh16[oB] = packhf(v2 * scale, v3 * scale);
            }
        }
    }
}

// ---------------- FA2 attention, fp16 single-term QK + fp16 PV --------------
#define KVT 64
#define ROWU 20   // smem row stride in u32 (80B padded)

__global__ __launch_bounds__(128, 2) void attn_kernel(float* __restrict__ xo)
{
    __shared__ __align__(16) u32 skk[2][KVT * ROWU];
    __shared__ __align__(16) u32 svv[2][KVT * ROWU];

    const int tid  = threadIdx.x;
    const int lane = tid & 31;
    const int w    = tid >> 5;
    const int bh   = blockIdx.y;           // b*NH + h
    const int bb   = bh >> 2, h = bh & 3;
    const int sq0  = blockIdx.x * 128 + w * 32;

    // ---- load Q fragments (fp16, pre-scaled) --------------------------------
    u32 qR[2][2][4];
    #pragma unroll
    for (int mi = 0; mi < 2; mi++) {
        size_t qb = ((size_t)bh * SEQ + sq0 + mi * 16 + (lane >> 2)) * 16;
        #pragma unroll
        for (int kt = 0; kt < 2; kt++) {
            int d0 = kt * 8 + (lane & 3);
            qR[mi][kt][0] = g_qf[qb + d0];
            qR[mi][kt][1] = g_qf[qb + 8 * 16 + d0];
            qR[mi][kt][2] = g_qf[qb + d0 + 4];
            qR[mi][kt][3] = g_qf[qb + 8 * 16 + d0 + 4];
        }
    }

    float o[2][4][4];
    #pragma unroll
    for (int mi = 0; mi < 2; mi++)
        #pragma unroll
        for (int dn = 0; dn < 4; dn++)
            #pragma unroll
            for (int e = 0; e < 4; e++) o[mi][dn][e] = 0.f;
    float mrow[2][2] = {{-1e30f, -1e30f}, {-1e30f, -1e30f}};
    float lrow[2][2] = {{0.f, 0.f}, {0.f, 0.f}};

    int srow[2], scq[2];
    #pragma unroll
    for (int j = 0; j < 2; j++) {
        int idx = tid + 128 * j;
        srow[j] = idx >> 2;
        scq[j]  = idx & 3;
    }
    const size_t kvbase = (size_t)bh * SEQ * 16;

    const int g  = lane >> 3;
    const int lr = lane & 7;
    const u32 bK0 = sptr(&skk[0][0]);
    const u32 bV0 = sptr(&svv[0][0]);
    const u32 bufstride = KVT * ROWU * 4;

    uint4 pk[2], pv[2];
    #pragma unroll
    for (int j = 0; j < 2; j++) {
        size_t go = kvbase + (size_t)srow[j] * 16 + scq[j] * 4;
        pk[j] = *reinterpret_cast<const uint4*>(g_kf + go);
        pv[j] = *reinterpret_cast<const uint4*>(g_vf + go);
    }
    #pragma unroll
    for (int j = 0; j < 2; j++) {
        u32 so = srow[j] * ROWU + scq[j] * 4;
        *reinterpret_cast<uint4*>(&skk[0][so]) = pk[j];
        *reinterpret_cast<uint4*>(&svv[0][so]) = pv[j];
    }
    __syncthreads();

    const int NT = SEQ / KVT;
    for (int t = 0; t < NT; t++) {
        const int buf = t & 1;
        const u32 bK = bK0 + buf * bufstride;
        const u32 bV = bV0 + buf * bufstride;

        if (t + 1 < NT) {
            #pragma unroll
            for (int j = 0; j < 2; j++) {
                size_t go = kvbase + (size_t)((t + 1) * KVT + srow[j]) * 16 + scq[j] * 4;
                pk[j] = *reinterpret_cast<const uint4*>(g_kf + go);
                pv[j] = *reinterpret_cast<const uint4*>(g_vf + go);
            }
        }

        float s[2][8][4];
        #pragma unroll
        for (int mi = 0; mi < 2; mi++)
            #pragma unroll
            for (int nt = 0; nt < 8; nt++)
                #pragma unroll
                for (int e = 0; e < 4; e++) s[mi][nt][e] = 0.f;

        #pragma unroll
        for (int kt = 0; kt < 2; kt++) {
            u32 bk_[8][2];
            #pragma unroll
            for (int ap = 0; ap < 4; ap++) {
                u32 off = (u32)((16 * ap + 8 * (g >> 1) + lr) * 80 + (kt * 16 + 8 * (g & 1)) * 2);
                ldsm4(bk_[2 * ap][0], bk_[2 * ap][1], bk_[2 * ap + 1][0], bk_[2 * ap + 1][1], bK + off);
            }
            #pragma unroll
            for (int mi = 0; mi < 2; mi++)
                #pragma unroll
                for (int nt = 0; nt < 8; nt++)
                    mma16816h(s[mi][nt], qR[mi][kt], bk_[nt]);
        }

        #pragma unroll
        for (int mi = 0; mi < 2; mi++) {
            float mx0 = -1e30f, mx1 = -1e30f;
            #pragma unroll
            for (int nt = 0; nt < 8; nt++) {
                mx0 = fmaxf(mx0, fmaxf(s[mi][nt][0], s[mi][nt][1]));
                mx1 = fmaxf(mx1, fmaxf(s[mi][nt][2], s[mi][nt][3]));
            }
            mx0 = fmaxf(mx0, __shfl_xor_sync(0xffffffffu, mx0, 1));
            mx0 = fmaxf(mx0, __shfl_xor_sync(0xffffffffu, mx0, 2));
            mx1 = fmaxf(mx1, __shfl_xor_sync(0xffffffffu, mx1, 1));
            mx1 = fmaxf(mx1, __shfl_xor_sync(0xffffffffu, mx1, 2));
            float mn0 = fmaxf(mrow[mi][0], mx0);
            float mn1 = fmaxf(mrow[mi][1], mx1);
            float al0 = exf(mrow[mi][0] - mn0);
            float al1 = exf(mrow[mi][1] - mn1);
            float sum0 = 0.f, sum1 = 0.f;
            #pragma unroll
            for (int nt = 0; nt < 8; nt++) {
                float p0 = exf(s[mi][nt][0] - mn0);
                float p1 = exf(s[mi][nt][1] - mn0);
                float p2 = exf(s[mi][nt][2] - mn1);
                float p3 = exf(s[mi][nt][3] - mn1);
                s[mi][nt][0] = p0; s[mi][nt][1] = p1;
                s[mi][nt][2] = p2; s[mi][nt][3] = p3;
                sum0 += p0 + p1; sum1 += p2 + p3;
            }
            sum0 += __shfl_xor_sync(0xffffffffu, sum0, 1);
            sum0 += __shfl_xor_sync(0xffffffffu, sum0, 2);
            sum1 += __shfl_xor_sync(0xffffffffu, sum1, 1);
            sum1 += __shfl_xor_sync(0xffffffffu, sum1, 2);
            lrow[mi][0] = lrow[mi][0] * al0 + sum0;
            lrow[mi][1] = lrow[mi][1] * al1 + sum1;
            mrow[mi][0] = mn0; mrow[mi][1] = mn1;
            #pragma unroll
            for (int dn = 0; dn < 4; dn++) {
                o[mi][dn][0] *= al0; o[mi][dn][1] *= al0;
                o[mi][dn][2] *= al1; o[mi][dn][3] *= al1;
            }
        }

        #pragma unroll
        for (int kt = 0; kt < 4; kt++) {
            u32 bv[4][2];
            #pragma unroll
            for (int dp = 0; dp < 2; dp++) {
                u32 off = (u32)((16 * kt + 8 * (g & 1) + lr) * 80 + (dp * 16 + 8 * (g >> 1)) * 2);
                ldsm4t(bv[2 * dp][0], bv[2 * dp][1], bv[2 * dp + 1][0], bv[2 * dp + 1][1], bV + off);
            }
            #pragma unroll
            for (int mi = 0; mi < 2; mi++) {
                u32 pa[4];
                pa[0] = packhf(s[mi][2 * kt][0],     s[mi][2 * kt][1]);
                pa[1] = packhf(s[mi][2 * kt][2],     s[mi][2 * kt][3]);
                pa[2] = packhf(s[mi][2 * kt + 1][0], s[mi][2 * kt + 1][1]);
                pa[3] = packhf(s[mi][2 * kt + 1][2], s[mi][2 * kt + 1][3]);
                #pragma unroll
                for (int dn = 0; dn < 4; dn++)
                    mma16816h(o[mi][dn], pa, bv[dn]);
            }
        }

        if (t + 1 < NT) {
            const int nb = (t + 1) & 1;
            #pragma unroll
            for (int j = 0; j < 2; j++) {
                u32 so = srow[j] * ROWU + scq[j] * 4;
                *reinterpret_cast<uint4*>(&skk[nb][so]) = pk[j];
                *reinterpret_cast<uint4*>(&svv[nb][so]) = pv[j];
            }
        }
        __syncthreads();
    }

    // ---- finalize & write ----------------------------------------------------
    #pragma unroll
    for (int mi = 0; mi < 2; mi++) {
        float inv0 = 1.0f / lrow[mi][0];
        float inv1 = 1.0f / lrow[mi][1];
        int r = bb * SEQ + sq0 + mi * 16 + (lane >> 2);
        #pragma unroll
        for (int dn = 0; dn < 4; dn++) {
            int cc = h * HD + dn * 8 + 2 * (lane & 3);
            float2 o0 = {o[mi][dn][0] * inv0, o[mi][dn][1] * inv0};
            float2 o1 = {o[mi][dn][2] * inv1, o[mi][dn][3] * inv1};
            *reinterpret_cast<float2*>(xo + (size_t)r * CCH + cc)       = o0;
            *reinterpret_cast<float2*>(xo + (size_t)(r + 8) * CCH + cc) = o1;
        }
    }
}

// ---------------- [B*S, C] -> [B, C, S] output transpose -------------------
__global__ __launch_bounds__(256) void out_transpose_kernel(
    const float* __restrict__ src, float* __restrict__ dst)
{
    __shared__ float t[32][33];
    const int tx = threadIdx.x, ty = threadIdx.y;
    const int s0 = blockIdx.x * 32;
    const int c0 = blockIdx.y * 32;
    const int bb = blockIdx.z;
    #pragma unroll
    for (int i = ty; i < 32; i += 8)
        t[i][tx] = src[((size_t)bb * SEQ + s0 + i) * CCH + c0 + tx];
    __syncthreads();
    #pragma unroll
    for (int i = ty; i < 32; i += 8)
        dst[(size_t)bb * CCH * SEQ + (size_t)(c0 + i) * SEQ + s0 + tx] = t[tx][i];
}

// ---------------- launch ----------------------------------------------------
static float* symf(const void* symbol) {
    void* p = nullptr;
    cudaGetSymbolAddress(&p, symbol);
    return reinterpret_cast<float*>(p);
}
static u32* symu(const void* symbol) {
    void* p = nullptr;
    cudaGetSymbolAddress(&p, symbol);
    return reinterpret_cast<u32*>(p);
}

extern "C" void kernel_launch(void* const* d_in, const int* in_sizes, int n_in,
                              void* d_out, int out_size)
{
    const float* q = (const float*)d_in[0];
    const float* k = (const float*)d_in[1];
    const float* v = (const float*)d_in[2];
    const float* ln_g[3]  = {(const float*)d_in[3],  (const float*)d_in[9],  (const float*)d_in[15]};
    const float* ln_b[3]  = {(const float*)d_in[4],  (const float*)d_in[10], (const float*)d_in[16]};
    const float* w1[3]    = {(const float*)d_in[5],  (const float*)d_in[11], (const float*)d_in[17]};
    const float* b1[3]    = {(const float*)d_in[6],  (const float*)d_in[12], (const float*)d_in[18]};
    const float* w2[3]    = {(const float*)d_in[7],  (const float*)d_in[13], (const float*)d_in[19]};
    const float* b2[3]    = {(const float*)d_in[8],  (const float*)d_in[14], (const float*)d_in[20]};
    const float* m1_w1 = (const float*)d_in[21];
    const float* m1_b1 = (const float*)d_in[22];
    const float* m1_w2 = (const float*)d_in[23];
    const float* m1_b2 = (const float*)d_in[24];
    const float* m2_w1 = (const float*)d_in[25];
    const float* m2_b1 = (const float*)d_in[26];
    const float* m2_w2 = (const float*)d_in[27];
    const float* m2_b2 = (const float*)d_in[28];

    float* qp  = symf(g_qp);
    float* vp  = symf(g_vp);
    float* x   = symf(g_x);
    float* rs1 = symf(g_rs1);
    float* hb  = symf(g_h);
    u32* qf = symu(g_qf);
    u32* kf = symu(g_kf);
    u32* vf = symu(g_vf);

    const float qsc = 1.44269504088896f / 5.65685424949238f;  // log2e/sqrt(32)

    dim3 g1(HID / 64, NTOK / 128);   // (4, 64)
    dim3 g2(CCH / 64, NTOK / 128);   // (2, 64)

    // q projection -> fp16 (scaled)
    ln_transpose_kernel<<<dim3(SEQ / 16, 2), 256>>>(q, ln_g[0], ln_b[0], x);
    gemm_bf16_kernel<true,  false, 0><<<g1, 128>>>(x,  w1[0], b1[0], nullptr, hb, nullptr, 0.f, NTOK, CCH, HID);
    gemm_bf16_kernel<false, false, 1><<<g2, 128>>>(hb, w2[0], b2[0], nullptr, nullptr, qf, qsc, NTOK, HID, CCH);

    // k projection -> fp16
    ln_transpose_kernel<<<dim3(SEQ / 16, 2), 256>>>(k, ln_g[1], ln_b[1], x);
    gemm_bf16_kernel<true,  false, 0><<<g1, 128>>>(x,  w1[1], b1[1], nullptr, hb, nullptr, 0.f, NTOK, CCH, HID);
    gemm_bf16_kernel<false, false, 1><<<g2, 128>>>(hb, w2[1], b2[1], nullptr, nullptr, kf, 1.f, NTOK, HID, CCH);

    // v projection -> fp32 (residual) + fp16 (PV)
    ln_transpose_kernel<<<dim3(SEQ / 16, 2), 256>>>(v, ln_g[2], ln_b[2], x);
    gemm_bf16_kernel<true,  false, 0><<<g1, 128>>>(x,  w1[2], b1[2], nullptr, hb, nullptr, 0.f, NTOK, CCH, HID);
    gemm_bf16_kernel<false, false, 2><<<g2, 128>>>(hb, w2[2], b2[2], nullptr, vp, vf, 1.f, NTOK, HID, CCH);

    attn_kernel<<<dim3(SEQ / 128, 2 * NH), 128>>>(x);

    gemm_bf16_kernel<true,  false, 0><<<g1, 128>>>(x,   m1_w1, m1_b1, nullptr, hb,  nullptr, 0.f, NTOK, CCH, HID);
    gemm_bf16_kernel<false, true,  0><<<g2, 128>>>(hb,  m1_w2, m1_b2, vp,      rs1, nullptr, 0.f, NTOK, HID, CCH);
    gemm_bf16_kernel<true,  false, 0><<<g1, 128>>>(rs1, m2_w1, m2_b1, nullptr, hb,  nullptr, 0.f, NTOK, CCH, HID);
    gemm_bf16_kernel<false, true,  0><<<g2, 128>>>(hb,  m2_w2, m2_b2, rs1,     qp,  nullptr, 0.f, NTOK, HID, CCH);

    out_transpose_kernel<<<dim3(SEQ / 32, CCH / 32, 2), dim3(32, 8)>>>(qp, (float*)d_out);
}

// round 9
// speedup vs baseline: 1.2357x; 1.0201x over previous
#include <cuda_runtime.h>
#include <cuda_bf16.h>
#include <cstdint>

#define NTOK 8192      // B*S
#define CCH  128       // C
#define HID  256       // 2C
#define SEQ  4096      // S per batch
#define NH   4
#define HD   32

typedef unsigned int u32;

// ---------------- scratch (static device memory, no allocs) ----------------
__device__ float g_qp [NTOK * CCH];
__device__ float g_vp [NTOK * CCH];
__device__ float g_x  [NTOK * CCH];
__device__ float g_rs1[NTOK * CCH];
__device__ float g_h  [NTOK * HID];
__device__ float g_x3 [3 * NTOK * CCH];
__device__ float g_h3 [3 * NTOK * HID];
// head-major fp16 operands: [b*NH+h][token][16 u32]
__device__ u32 g_qf[2 * NH * SEQ * 16];
__device__ u32 g_kf[2 * NH * SEQ * 16];
__device__ u32 g_vf[2 * NH * SEQ * 16];

struct Ptrs3  { const float* p[3]; };
struct LNIn   { const float* x[3]; const float* g[3]; const float* b[3]; };
struct QKVOut { u32* o16[3]; float sc[3]; float* vC; };

// ---------------- pack helpers ----------------------------------------------
__device__ __forceinline__ u32 packbf_tr(float x, float y) {   // truncation hi
    return (__float_as_uint(y) & 0xffff0000u) | (__float_as_uint(x) >> 16);
}
__device__ __forceinline__ float trhi(float x) {
    return __uint_as_float(__float_as_uint(x) & 0xffff0000u);
}
__device__ __forceinline__ u32 packbf_rn(float x, float y) {
    u32 d; asm("cvt.rn.bf16x2.f32 %0,%2,%1;" : "=r"(d) : "f"(x), "f"(y)); return d;
}
__device__ __forceinline__ u32 packhf(float x, float y) {      // fp16x2, x->low
    u32 d; asm("cvt.rn.f16x2.f32 %0,%2,%1;" : "=r"(d) : "f"(x), "f"(y)); return d;
}
__device__ __forceinline__ float exf(float x) {                // MUFU exp2
    float r; asm("ex2.approx.f32 %0,%1;" : "=f"(r) : "f"(x)); return r;
}
__device__ __forceinline__ u32 sptr(const void* p) {
    u32 a; asm("{.reg .u64 t; cvta.to.shared.u64 t,%1; cvt.u32.u64 %0,t;}" : "=r"(a) : "l"(p));
    return a;
}

// ---------------- mma / ldmatrix wrappers -----------------------------------
__device__ __forceinline__ void mma16816(float* c, const u32* a, const u32* b) {  // bf16
    asm volatile(
        "mma.sync.aligned.m16n8k16.row.col.f32.bf16.bf16.f32 "
        "{%0,%1,%2,%3},{%4,%5,%6,%7},{%8,%9},{%0,%1,%2,%3};"
        : "+f"(c[0]), "+f"(c[1]), "+f"(c[2]), "+f"(c[3])
        : "r"(a[0]), "r"(a[1]), "r"(a[2]), "r"(a[3]), "r"(b[0]), "r"(b[1]));
}
__device__ __forceinline__ void mma16816h(float* c, const u32* a, const u32* b) { // fp16
    asm volatile(
        "mma.sync.aligned.m16n8k16.row.col.f32.f16.f16.f32 "
        "{%0,%1,%2,%3},{%4,%5,%6,%7},{%8,%9},{%0,%1,%2,%3};"
        : "+f"(c[0]), "+f"(c[1]), "+f"(c[2]), "+f"(c[3])
        : "r"(a[0]), "r"(a[1]), "r"(a[2]), "r"(a[3]), "r"(b[0]), "r"(b[1]));
}
__device__ __forceinline__ void ldsm4(u32& r0, u32& r1, u32& r2, u32& r3, u32 addr) {
    asm volatile("ldmatrix.sync.aligned.m8n8.x4.shared.b16 {%0,%1,%2,%3},[%4];"
                 : "=r"(r0), "=r"(r1), "=r"(r2), "=r"(r3) : "r"(addr));
}
__device__ __forceinline__ void ldsm4t(u32& r0, u32& r1, u32& r2, u32& r3, u32 addr) {
    asm volatile("ldmatrix.sync.aligned.m8n8.x4.trans.shared.b16 {%0,%1,%2,%3},[%4];"
                 : "=r"(r0), "=r"(r1), "=r"(r2), "=r"(r3) : "r"(addr));
}

// ---------------- LayerNorm + transpose, batched over q/k/v ------------------
__global__ __launch_bounds__(256) void ln_transpose_kernel(LNIn in, float* __restrict__ y3)
{
    __shared__ float tile[CCH][17];
    const int z   = blockIdx.z;
    const float* x   = in.x[z];
    const float* gam = in.g[z];
    const float* bet = in.b[z];
    float* y = y3 + (size_t)z * NTOK * CCH;

    const int tid = threadIdx.x;
    const int s0  = blockIdx.x * 16;
    const int bb  = blockIdx.y;

    #pragma unroll
    for (int it = 0; it < 8; it++) {
        int idx = tid + it * 256;
        int c = idx >> 4, t = idx & 15;
        tile[c][t] = x[(size_t)bb * CCH * SEQ + (size_t)c * SEQ + s0 + t];
    }
    __syncthreads();

    const int w = tid >> 5, lane = tid & 31;
    #pragma unroll
    for (int rep = 0; rep < 2; rep++) {
        int t = w * 2 + rep;
        float sum = 0.f, sq = 0.f;
        #pragma unroll
        for (int j = 0; j < 4; j++) {
            float v = tile[lane + 32 * j][t];
            sum += v; sq += v * v;
        }
        #pragma unroll
        for (int off = 16; off > 0; off >>= 1) {
            sum += __shfl_xor_sync(0xffffffffu, sum, off);
            sq  += __shfl_xor_sync(0xffffffffu, sq,  off);
        }
        float mu   = sum * (1.0f / CCH);
        float var  = sq * (1.0f / CCH) - mu * mu;
        float rstd = rsqrtf(var + 1e-5f);
        size_t row = ((size_t)bb * SEQ + s0 + t) * CCH;
        #pragma unroll
        for (int j = 0; j < 4; j++) {
            int c = lane + 32 * j;
            y[row + c] = (tile[c][t] - mu) * rstd * gam[c] + bet[c];
        }
    }
}

#define AROW 12
#define BROW 36

// ---------------- single-term fp16 GEMM, batched over z (q/k/v) --------------
// QKV=false: fp32 out (Cbase + z*Cstride).  QKV=true: fp16 head-major (+v fp32)
template <bool LEAKY, bool QKV>
__global__ __launch_bounds__(128, 2) void gemm_h1_kernel(
    const float* __restrict__ Abase, long Astride,
    Ptrs3 W, Ptrs3 Bi,
    float* __restrict__ Cbase, long Cstride,
    QKVOut qo, int K, int M)
{
    __shared__ __align__(16) u32 sA[2][128 * AROW];
    __shared__ __align__(16) u32 sB[2][16 * BROW];

    const int z = blockIdx.z;
    const float* A    = Abase + (size_t)z * Astride;
    const float* Bw   = W.p[z];
    const float* bias = Bi.p[z];

    const int tid  = threadIdx.x;
    const int lane = tid & 31;
    const int w    = tid >> 5;
    const int n0 = blockIdx.y * 128;
    const int m0 = blockIdx.x * 64;

    const int g  = lane >> 3;
    const int lr = lane & 7;

    int arow[4], acol[4];
    #pragma unroll
    for (int j = 0; j < 4; j++) {
        int idx = tid + 128 * j;
        arow[j] = idx >> 2;
        acol[j] = idx & 3;
    }
    int brow[2], bcol[2];
    #pragma unroll
    for (int j = 0; j < 2; j++) {
        int idx = tid + 128 * j;
        brow[j] = idx >> 4;
        bcol[j] = idx & 15;
    }

    float c[2][8][4];
    #pragma unroll
    for (int mi = 0; mi < 2; mi++)
        #pragma unroll
        for (int nt = 0; nt < 8; nt++)
            #pragma unroll
            for (int e = 0; e < 4; e++) c[mi][nt][e] = 0.f;

    const u32 bA0 = sptr(&sA[0][0]);
    const u32 bB0 = sptr(&sB[0][0]);
    const u32 abuf = 128 * AROW * 4;
    const u32 bbuf = 16 * BROW * 4;

    const int NT = K >> 4;

    float4 af[4], bf4[2];
    #pragma unroll
    for (int j = 0; j < 4; j++)
        af[j] = *reinterpret_cast<const float4*>(&A[(size_t)(n0 + arow[j]) * K + acol[j] * 4]);
    #pragma unroll
    for (int j = 0; j < 2; j++)
        bf4[j] = *reinterpret_cast<const float4*>(&Bw[(size_t)brow[j] * M + m0 + bcol[j] * 4]);

    #pragma unroll
    for (int j = 0; j < 4; j++) {
        int o = arow[j] * AROW + acol[j] * 2;
        sA[0][o]     = packhf(af[j].x, af[j].y);
        sA[0][o + 1] = packhf(af[j].z, af[j].w);
    }
    #pragma unroll
    for (int j = 0; j < 2; j++) {
        int o = brow[j] * BROW + bcol[j] * 2;
        sB[0][o]     = packhf(bf4[j].x, bf4[j].y);
        sB[0][o + 1] = packhf(bf4[j].z, bf4[j].w);
    }
    __syncthreads();

    for (int t = 0; t < NT; t++) {
        const int buf = t & 1;
        const u32 aS = bA0 + buf * abuf;
        const u32 bS = bB0 + buf * bbuf;

        if (t + 1 < NT) {
            int k0 = (t + 1) * 16;
            #pragma unroll
            for (int j = 0; j < 4; j++)
                af[j] = *reinterpret_cast<const float4*>(&A[(size_t)(n0 + arow[j]) * K + k0 + acol[j] * 4]);
            #pragma unroll
            for (int j = 0; j < 2; j++)
                bf4[j] = *reinterpret_cast<const float4*>(&Bw[(size_t)(k0 + brow[j]) * M + m0 + bcol[j] * 4]);
        }

        u32 aF[2][4];
        #pragma unroll
        for (int mi = 0; mi < 2; mi++) {
            u32 off = (u32)((w * 32 + mi * 16 + (g & 1) * 8 + lr) * 48 + (g >> 1) * 16);
            ldsm4(aF[mi][0], aF[mi][1], aF[mi][2], aF[mi][3], aS + off);
        }
        u32 bF[8][2];
        #pragma unroll
        for (int dp = 0; dp < 4; dp++) {
            u32 off = (u32)((8 * (g & 1) + lr) * 144 + (dp * 16 + 8 * (g >> 1)) * 2);
            ldsm4t(bF[2 * dp][0], bF[2 * dp][1], bF[2 * dp + 1][0], bF[2 * dp + 1][1], bS + off);
        }

        #pragma unroll
        for (int mi = 0; mi < 2; mi++)
            #pragma unroll
            for (int nt = 0; nt < 8; nt++)
                mma16816h(c[mi][nt], aF[mi], bF[nt]);

        if (t + 1 < NT) {
            const int nb = (t + 1) & 1;
            #pragma unroll
            for (int j = 0; j < 4; j++) {
                int o = arow[j] * AROW + acol[j] * 2;
                sA[nb][o]     = packhf(af[j].x, af[j].y);
                sA[nb][o + 1] = packhf(af[j].z, af[j].w);
            }
            #pragma unroll
            for (int j = 0; j < 2; j++) {
                int o = brow[j] * BROW + bcol[j] * 2;
                sB[nb][o]     = packhf(bf4[j].x, bf4[j].y);
                sB[nb][o + 1] = packhf(bf4[j].z, bf4[j].w);
            }
        }
        __syncthreads();
    }

    // ---- epilogue -----------------------------------------------------------
    #pragma unroll
    for (int mi = 0; mi < 2; mi++) {
        int r0 = n0 + w * 32 + mi * 16 + (lane >> 2);
        #pragma unroll
        for (int nt = 0; nt < 8; nt++) {
            int col = m0 + nt * 8 + (lane & 3) * 2;
            float2 bb = *reinterpret_cast<const float2*>(&bias[col]);
            float v0 = c[mi][nt][0] + bb.x;
            float v1 = c[mi][nt][1] + bb.y;
            float v2 = c[mi][nt][2] + bb.x;
            float v3 = c[mi][nt][3] + bb.y;
            if (LEAKY) {
                v0 = fmaxf(v0, 0.f) + 0.01f * fminf(v0, 0.f);
                v1 = fmaxf(v1, 0.f) + 0.01f * fminf(v1, 0.f);
                v2 = fmaxf(v2, 0.f) + 0.01f * fminf(v2, 0.f);
                v3 = fmaxf(v3, 0.f) + 0.01f * fminf(v3, 0.f);
            }
            if (!QKV) {
                float* C = Cbase + (size_t)z * Cstride;
                *reinterpret_cast<float2*>(&C[(size_t)r0 * M + col])       = make_float2(v0, v1);
                *reinterpret_cast<float2*>(&C[(size_t)(r0 + 8) * M + col]) = make_float2(v2, v3);
            } else {
                int h = col >> 5, dpair = (col & 31) >> 1;
                int bI = r0 >> 12, sI = r0 & (SEQ - 1);
                size_t oA = ((size_t)(bI * NH + h) * SEQ + sI) * 16 + dpair;
                size_t oB = oA + 8 * 16;
                u32* o16 = qo.o16[z];
                float sc = qo.sc[z];
                o16[oA] = packhf(v0 * sc, v1 * sc);
                o16[oB] = packhf(v2 * sc, v3 * sc);
                if (z == 2) {
                    *reinterpret_cast<float2*>(&qo.vC[(size_t)r0 * M + col])       = make_float2(v0, v1);
                    *reinterpret_cast<float2*>(&qo.vC[(size_t)(r0 + 8) * M + col]) = make_float2(v2, v3);
                }
            }
        }
    }
}

// ---------------- 3-term split-bf16 GEMM (MLP path, from R7) ------------------
template <bool LEAKY, bool RES>
__global__ __launch_bounds__(128) void gemm_bf16_kernel(
    const float* __restrict__ A, const float* __restrict__ B,
    const float* __restrict__ bias, const float* __restrict__ res,
    float* __restrict__ C, int N, int K, int M)
{
    __shared__ __align__(16) u32 sAhi[2][128 * AROW];
    __shared__ __align__(16) u32 sAlo[2][128 * AROW];
    __shared__ __align__(16) u32 sBhi[2][16 * BROW];
    __shared__ __align__(16) u32 sBlo[2][16 * BROW];

    const int tid  = threadIdx.x;
    const int lane = tid & 31;
    const int w    = tid >> 5;
    const int n0 = blockIdx.y * 128;
    const int m0 = blockIdx.x * 64;

    const int g  = lane >> 3;
    const int lr = lane & 7;

    int arow[4], acol[4];
    #pragma unroll
    for (int j = 0; j < 4; j++) {
        int idx = tid + 128 * j;
        arow[j] = idx >> 2;
        acol[j] = idx & 3;
    }
    int brow[2], bcol[2];
    #pragma unroll
    for (int j = 0; j < 2; j++) {
        int idx = tid + 128 * j;
        brow[j] = idx >> 4;
        bcol[j] = idx & 15;
    }

    float c[2][8][4];
    #pragma unroll
    for (int mi = 0; mi < 2; mi++)
        #pragma unroll
        for (int nt = 0; nt < 8; nt++)
            #pragma unroll
            for (int e = 0; e < 4; e++) c[mi][nt][e] = 0.f;

    const u32 bA0 = sptr(&sAhi[0][0]);
    const u32 bAl0 = sptr(&sAlo[0][0]);
    const u32 bB0 = sptr(&sBhi[0][0]);
    const u32 bBl0 = sptr(&sBlo[0][0]);
    const u32 abuf = 128 * AROW * 4;
    const u32 bbuf = 16 * BROW * 4;

    const int NT = K >> 4;

    float4 af[4], bf4[2];
    #pragma unroll
    for (int j = 0; j < 4; j++)
        af[j] = *reinterpret_cast<const float4*>(&A[(size_t)(n0 + arow[j]) * K + acol[j] * 4]);
    #pragma unroll
    for (int j = 0; j < 2; j++)
        bf4[j] = *reinterpret_cast<const float4*>(&B[(size_t)brow[j] * M + m0 + bcol[j] * 4]);

    #pragma unroll
    for (int j = 0; j < 4; j++) {
        int o = arow[j] * AROW + acol[j] * 2;
        float4 f = af[j];
        sAhi[0][o]     = packbf_tr(f.x, f.y);
        sAhi[0][o + 1] = packbf_tr(f.z, f.w);
        sAlo[0][o]     = packbf_rn(f.x - trhi(f.x), f.y - trhi(f.y));
        sAlo[0][o + 1] = packbf_rn(f.z - trhi(f.z), f.w - trhi(f.w));
    }
    #pragma unroll
    for (int j = 0; j < 2; j++) {
        int o = brow[j] * BROW + bcol[j] * 2;
        float4 f = bf4[j];
        sBhi[0][o]     = packbf_tr(f.x, f.y);
        sBhi[0][o + 1] = packbf_tr(f.z, f.w);
        sBlo[0][o]     = packbf_rn(f.x - trhi(f.x), f.y - trhi(f.y));
        sBlo[0][o + 1] = packbf_rn(f.z - trhi(f.z), f.w - trhi(f.w));
    }
    __syncthreads();

    for (int t = 0; t < NT; t++) {
        const int buf = t & 1;
        const u32 aH = bA0  + buf * abuf;
        const u32 aL = bAl0 + buf * abuf;
        const u32 bH = bB0  + buf * bbuf;
        const u32 bL = bBl0 + buf * bbuf;

        if (t + 1 < NT) {
            int k0 = (t + 1) * 16;
            #pragma unroll
            for (int j = 0; j < 4; j++)
                af[j] = *reinterpret_cast<const float4*>(&A[(size_t)(n0 + arow[j]) * K + k0 + acol[j] * 4]);
            #pragma unroll
            for (int j = 0; j < 2; j++)
                bf4[j] = *reinterpret_cast<const float4*>(&B[(size_t)(k0 + brow[j]) * M + m0 + bcol[j] * 4]);
        }

        u32 ahi[2][4], alo[2][4];
        #pragma unroll
        for (int mi = 0; mi < 2; mi++) {
            u32 off = (u32)((w * 32 + mi * 16 + (g & 1) * 8 + lr) * 48 + (g >> 1) * 16);
            ldsm4(ahi[mi][0], ahi[mi][1], ahi[mi][2], ahi[mi][3], aH + off);
            ldsm4(alo[mi][0], alo[mi][1], alo[mi][2], alo[mi][3], aL + off);
        }
        u32 bhi[8][2], blo[8][2];
        #pragma unroll
        for (int dp = 0; dp < 4; dp++) {
            u32 off = (u32)((8 * (g & 1) + lr) * 144 + (dp * 16 + 8 * (g >> 1)) * 2);
            ldsm4t(bhi[2 * dp][0], bhi[2 * dp][1], bhi[2 * dp + 1][0], bhi[2 * dp + 1][1], bH + off);
            ldsm4t(blo[2 * dp][0], blo[2 * dp][1], blo[2 * dp + 1][0], blo[2 * dp + 1][1], bL + off);
        }

        #pragma unroll
        for (int mi = 0; mi < 2; mi++)
            #pragma unroll
            for (int nt = 0; nt < 8; nt++) {
                mma16816(c[mi][nt], ahi[mi], bhi[nt]);
                mma16816(c[mi][nt], ahi[mi], blo[nt]);
                mma16816(c[mi][nt], alo[mi], bhi[nt]);
            }

        if (t + 1 < NT) {
            const int nb = (t + 1) & 1;
            #pragma unroll
            for (int j = 0; j < 4; j++) {
                int o = arow[j] * AROW + acol[j] * 2;
                float4 f = af[j];
                sAhi[nb][o]     = packbf_tr(f.x, f.y);
                sAhi[nb][o + 1] = packbf_tr(f.z, f.w);
                sAlo[nb][o]     = packbf_rn(f.x - trhi(f.x), f.y - trhi(f.y));
                sAlo[nb][o + 1] = packbf_rn(f.z - trhi(f.z), f.w - trhi(f.w));
            }
            #pragma unroll
            for (int j = 0; j < 2; j++) {
                int o = brow[j] * BROW + bcol[j] * 2;
                float4 f = bf4[j];
                sBhi[nb][o]     = packbf_tr(f.x, f.y);
                sBhi[nb][o + 1] = packbf_tr(f.z, f.w);
                sBlo[nb][o]     = packbf_rn(f.x - trhi(f.x), f.y - trhi(f.y));
                sBlo[nb][o + 1] = packbf_rn(f.z - trhi(f.z), f.w - trhi(f.w));
            }
        }
        __syncthreads();
    }

    #pragma unroll
    for (int mi = 0; mi < 2; mi++) {
        int r0 = n0 + w * 32 + mi * 16 + (lane >> 2);
        #pragma unroll
        for (int nt = 0; nt < 8; nt++) {
            int col = m0 + nt * 8 + (lane & 3) * 2;
            float2 bb = *reinterpret_cast<const float2*>(&bias[col]);
            float v0 = c[mi][nt][0] + bb.x;
            float v1 = c[mi][nt][1] + bb.y;
            float v2 = c[mi][nt][2] + bb.x;
            float v3 = c[mi][nt][3] + bb.y;
            if (LEAKY) {
                v0 = fmaxf(v0, 0.f) + 0.01f * fminf(v0, 0.f);
                v1 = fmaxf(v1, 0.f) + 0.01f * fminf(v1, 0.f);
                v2 = fmaxf(v2, 0.f) + 0.01f * fminf(v2, 0.f);
                v3 = fmaxf(v3, 0.f) + 0.01f * fminf(v3, 0.f);
            }
            if (RES) {
                float2 r4a = *reinterpret_cast<const float2*>(&res[(size_t)r0 * M + col]);
                float2 r4b = *reinterpret_cast<const float2*>(&res[(size_t)(r0 + 8) * M + col]);
                v0 += r4a.x; v1 += r4a.y; v2 += r4b.x; v3 += r4b.y;
            }
            *reinterpret_cast<float2*>(&C[(size_t)r0 * M + col])       = make_float2(v0, v1);
            *reinterpret_cast<float2*>(&C[(size_t)(r0 + 8) * M + col]) = make_float2(v2, v3);
        }
    }
}

// ---------------- FA2 attention (R7, passing) --------------------------------
#define KVT 64
#define ROWU 20

__global__ __launch_bounds__(128, 2) void attn_kernel(float* __restrict__ xo)
{
    __shared__ __align__(16) u32 skk[2][KVT * ROWU];
    __shared__ __align__(16) u32 svv[2][KVT * ROWU];

    const int tid  = threadIdx.x;
    const int lane = tid & 31;
    const int w    = tid >> 5;
    const int bh   = blockIdx.y;
    const int bb   = bh >> 2, h = bh & 3;
    const int sq0  = blockIdx.x * 128 + w * 32;

    u32 qR[2][2][4];
    #pragma unroll
    for (int mi = 0; mi < 2; mi++) {
        size_t qb = ((size_t)bh * SEQ + sq0 + mi * 16 + (lane >> 2)) * 16;
        #pragma unroll
        for (int kt = 0; kt < 2; kt++) {
            int d0 = kt * 8 + (lane & 3);
            qR[mi][kt][0] = g_qf[qb + d0];
            qR[mi][kt][1] = g_qf[qb + 8 * 16 + d0];
            qR[mi][kt][2] = g_qf[qb + d0 + 4];
            qR[mi][kt][3] = g_qf[qb + 8 * 16 + d0 + 4];
        }
    }

    float o[2][4][4];
    #pragma unroll
    for (int mi = 0; mi < 2; mi++)
        #pragma unroll
        for (int dn = 0; dn < 4; dn++)
            #pragma unroll
            for (int e = 0; e < 4; e++) o[mi][dn][e] = 0.f;
    float mrow[2][2] = {{-1e30f, -1e30f}, {-1e30f, -1e30f}};
    float lrow[2][2] = {{0.f, 0.f}, {0.f, 0.f}};

    int srow[2], scq[2];
    #pragma unroll
    for (int j = 0; j < 2; j++) {
        int idx = tid + 128 * j;
        srow[j] = idx >> 2;
        scq[j]  = idx & 3;
    }
    const size_t kvbase = (size_t)bh * SEQ * 16;

    const int g  = lane >> 3;
    const int lr = lane & 7;
    const u32 bK0 = sptr(&skk[0][0]);
    const u32 bV0 = sptr(&svv[0][0]);
    const u32 bufstride = KVT * ROWU * 4;

    uint4 pk[2], pv[2];
    #pragma unroll
    for (int j = 0; j < 2; j++) {
        size_t go = kvbase + (size_t)srow[j] * 16 + scq[j] * 4;
        pk[j] = *reinterpret_cast<const uint4*>(g_kf + go);
        pv[j] = *reinterpret_cast<const uint4*>(g_vf + go);
    }
    #pragma unroll
    for (int j = 0; j < 2; j++) {
        u32 so = srow[j] * ROWU + scq[j] * 4;
        *reinterpret_cast<uint4*>(&skk[0][so]) = pk[j];
        *reinterpret_cast<uint4*>(&svv[0][so]) = pv[j];
    }
    __syncthreads();

    const int NT = SEQ / KVT;
    for (int t = 0; t < NT; t++) {
        const int buf = t & 1;
        const u32 bK = bK0 + buf * bufstride;
        const u32 bV = bV0 + buf * bufstride;

        if (t + 1 < NT) {
            #pragma unroll
            for (int j = 0; j < 2; j++) {
                size_t go = kvbase + (size_t)((t + 1) * KVT + srow[j]) * 16 + scq[j] * 4;
                pk[j] = *reinterpret_cast<const uint4*>(g_kf + go);
                pv[j] = *reinterpret_cast<const uint4*>(g_vf + go);
            }
        }

        float s[2][8][4];
        #pragma unroll
        for (int mi = 0; mi < 2; mi++)
            #pragma unroll
            for (int nt = 0; nt < 8; nt++)
                #pragma unroll
                for (int e = 0; e < 4; e++) s[mi][nt][e] = 0.f;

        #pragma unroll
        for (int kt = 0; kt < 2; kt++) {
            u32 bk_[8][2];
            #pragma unroll
            for (int ap = 0; ap < 4; ap++) {
                u32 off = (u32)((16 * ap + 8 * (g >> 1) + lr) * 80 + (kt * 16 + 8 * (g & 1)) * 2);
                ldsm4(bk_[2 * ap][0], bk_[2 * ap][1], bk_[2 * ap + 1][0], bk_[2 * ap + 1][1], bK + off);
            }
            #pragma unroll
            for (int mi = 0; mi < 2; mi++)
                #pragma unroll
                for (int nt = 0; nt < 8; nt++)
                    mma16816h(s[mi][nt], qR[mi][kt], bk_[nt]);
        }

        #pragma unroll
        for (int mi = 0; mi < 2; mi++) {
            float mx0 = -1e30f, mx1 = -1e30f;
            #pragma unroll
            for (int nt = 0; nt < 8; nt++) {
                mx0 = fmaxf(mx0, fmaxf(s[mi][nt][0], s[mi][nt][1]));
                mx1 = fmaxf(mx1, fmaxf(s[mi][nt][2], s[mi][nt][3]));
            }
            mx0 = fmaxf(mx0, __shfl_xor_sync(0xffffffffu, mx0, 1));
            mx0 = fmaxf(mx0, __shfl_xor_sync(0xffffffffu, mx0, 2));
            mx1 = fmaxf(mx1, __shfl_xor_sync(0xffffffffu, mx1, 1));
            mx1 = fmaxf(mx1, __shfl_xor_sync(0xffffffffu, mx1, 2));
            float mn0 = fmaxf(mrow[mi][0], mx0);
            float mn1 = fmaxf(mrow[mi][1], mx1);
            float al0 = exf(mrow[mi][0] - mn0);
            float al1 = exf(mrow[mi][1] - mn1);
            float sum0 = 0.f, sum1 = 0.f;
            #pragma unroll
            for (int nt = 0; nt < 8; nt++) {
                float p0 = exf(s[mi][nt][0] - mn0);
                float p1 = exf(s[mi][nt][1] - mn0);
                float p2 = exf(s[mi][nt][2] - mn1);
                float p3 = exf(s[mi][nt][3] - mn1);
                s[mi][nt][0] = p0; s[mi][nt][1] = p1;
                s[mi][nt][2] = p2; s[mi][nt][3] = p3;
                sum0 += p0 + p1; sum1 += p2 + p3;
            }
            sum0 += __shfl_xor_sync(0xffffffffu, sum0, 1);
            sum0 += __shfl_xor_sync(0xffffffffu, sum0, 2);
            sum1 += __shfl_xor_sync(0xffffffffu, sum1, 1);
            sum1 += __shfl_xor_sync(0xffffffffu, sum1, 2);
            lrow[mi][0] = lrow[mi][0] * al0 + sum0;
            lrow[mi][1] = lrow[mi][1] * al1 + sum1;
            mrow[mi][0] = mn0; mrow[mi][1] = mn1;
            #pragma unroll
            for (int dn = 0; dn < 4; dn++) {
                o[mi][dn][0] *= al0; o[mi][dn][1] *= al0;
                o[mi][dn][2] *= al1; o[mi][dn][3] *= al1;
            }
        }

        #pragma unroll
        for (int kt = 0; kt < 4; kt++) {
            u32 bv[4][2];
            #pragma unroll
            for (int dp = 0; dp < 2; dp++) {
                u32 off = (u32)((16 * kt + 8 * (g & 1) + lr) * 80 + (dp * 16 + 8 * (g >> 1)) * 2);
                ldsm4t(bv[2 * dp][0], bv[2 * dp][1], bv[2 * dp + 1][0], bv[2 * dp + 1][1], bV + off);
            }
            #pragma unroll
            for (int mi = 0; mi < 2; mi++) {
                u32 pa[4];
                pa[0] = packhf(s[mi][2 * kt][0],     s[mi][2 * kt][1]);
                pa[1] = packhf(s[mi][2 * kt][2],     s[mi][2 * kt][3]);
                pa[2] = packhf(s[mi][2 * kt + 1][0], s[mi][2 * kt + 1][1]);
                pa[3] = packhf(s[mi][2 * kt + 1][2], s[mi][2 * kt + 1][3]);
                #pragma unroll
                for (int dn = 0; dn < 4; dn++)
                    mma16816h(o[mi][dn], pa, bv[dn]);
            }
        }

        if (t + 1 < NT) {
            const int nb = (t + 1) & 1;
            #pragma unroll
            for (int j = 0; j < 2; j++) {
                u32 so = srow[j] * ROWU + scq[j] * 4;
                *reinterpret_cast<uint4*>(&skk[nb][so]) = pk[j];
                *reinterpret_cast<uint4*>(&svv[nb][so]) = pv[j];
            }
        }
        __syncthreads();
    }

    #pragma unroll
    for (int mi = 0; mi < 2; mi++) {
        float inv0 = 1.0f / lrow[mi][0];
        float inv1 = 1.0f / lrow[mi][1];
        int r = bb * SEQ + sq0 + mi * 16 + (lane >> 2);
        #pragma unroll
        for (int dn = 0; dn < 4; dn++) {
            int cc = h * HD + dn * 8 + 2 * (lane & 3);
            float2 o0 = {o[mi][dn][0] * inv0, o[mi][dn][1] * inv0};
            float2 o1 = {o[mi][dn][2] * inv1, o[mi][dn][3] * inv1};
            *reinterpret_cast<float2*>(xo + (size_t)r * CCH + cc)       = o0;
            *reinterpret_cast<float2*>(xo + (size_t)(r + 8) * CCH + cc) = o1;
        }
    }
}

// ---------------- [B*S, C] -> [B, C, S] output transpose -------------------
__global__ __launch_bounds__(256) void out_transpose_kernel(
    const float* __restrict__ src, float* __restrict__ dst)
{
    __shared__ float t[32][33];
    const int tx = threadIdx.x, ty = threadIdx.y;
    const int s0 = blockIdx.x * 32;
    const int c0 = blockIdx.y * 32;
    const int bb = blockIdx.z;
    #pragma unroll
    for (int i = ty; i < 32; i += 8)
        t[i][tx] = src[((size_t)bb * SEQ + s0 + i) * CCH + c0 + tx];
    __syncthreads();
    #pragma unroll
    for (int i = ty; i < 32; i += 8)
        dst[(size_t)bb * CCH * SEQ + (size_t)(c0 + i) * SEQ + s0 + tx] = t[tx][i];
}

// ---------------- launch ----------------------------------------------------
static float* symf(const void* symbol) {
    void* p = nullptr;
    cudaGetSymbolAddress(&p, symbol);
    return reinterpret_cast<float*>(p);
}
static u32* symu(const void* symbol) {
    void* p = nullptr;
    cudaGetSymbolAddress(&p, symbol);
    return reinterpret_cast<u32*>(p);
}

extern "C" void kernel_launch(void* const* d_in, const int* in_sizes, int n_in,
                              void* d_out, int out_size)
{
    const float* q = (const float*)d_in[0];
    const float* k = (const float*)d_in[1];
    const float* v = (const float*)d_in[2];
    const float* ln_g[3]  = {(const float*)d_in[3],  (const float*)d_in[9],  (const float*)d_in[15]};
    const float* ln_b[3]  = {(const float*)d_in[4],  (const float*)d_in[10], (const float*)d_in[16]};
    const float* w1[3]    = {(const float*)d_in[5],  (const float*)d_in[11], (const float*)d_in[17]};
    const float* b1[3]    = {(const float*)d_in[6],  (const float*)d_in[12], (const float*)d_in[18]};
    const float* w2[3]    = {(const float*)d_in[7],  (const float*)d_in[13], (const float*)d_in[19]};
    const float* b2[3]    = {(const float*)d_in[8],  (const float*)d_in[14], (const float*)d_in[20]};
    const float* m1_w1 = (const float*)d_in[21];
    const float* m1_b1 = (const float*)d_in[22];
    const float* m1_w2 = (const float*)d_in[23];
    const float* m1_b2 = (const float*)d_in[24];
    const float* m2_w1 = (const float*)d_in[25];
    const float* m2_b1 = (const float*)d_in[26];
    const float* m2_w2 = (const float*)d_in[27];
    const float* m2_b2 = (const float*)d_in[28];

    float* qp  = symf(g_qp);
    float* vp  = symf(g_vp);
    float* x   = symf(g_x);
    float* rs1 = symf(g_rs1);
    float* hb  = symf(g_h);
    float* x3  = symf(g_x3);
    float* h3  = symf(g_h3);
    u32* qf = symu(g_qf);
    u32* kf = symu(g_kf);
    u32* vf = symu(g_vf);

    const float qsc = 1.44269504088896f / 5.65685424949238f;  // log2e/sqrt(32)

    // ---- batched LN for q,k,v ----
    LNIn lp;
    lp.x[0] = q; lp.x[1] = k; lp.x[2] = v;
    for (int i = 0; i < 3; i++) { lp.g[i] = ln_g[i]; lp.b[i] = ln_b[i]; }
    ln_transpose_kernel<<<dim3(SEQ / 16, 2, 3), 256>>>(lp, x3);

    // ---- batched GEMM1 (C->2C, LeakyReLU) ----
    Ptrs3 W1 = {{w1[0], w1[1], w1[2]}};
    Ptrs3 B1 = {{b1[0], b1[1], b1[2]}};
    QKVOut dummy = {{nullptr, nullptr, nullptr}, {0.f, 0.f, 0.f}, nullptr};
    gemm_h1_kernel<true, false><<<dim3(HID / 64, NTOK / 128, 3), 128>>>(
        x3, (long)NTOK * CCH, W1, B1, h3, (long)NTOK * HID, dummy, CCH, HID);

    // ---- batched GEMM2 (2C->C, fp16 head-major out; v also fp32) ----
    Ptrs3 W2 = {{w2[0], w2[1], w2[2]}};
    Ptrs3 B2 = {{b2[0], b2[1], b2[2]}};
    QKVOut qo = {{qf, kf, vf}, {qsc, 1.f, 1.f}, vp};
    gemm_h1_kernel<false, true><<<dim3(CCH / 64, NTOK / 128, 3), 128>>>(
        h3, (long)NTOK * HID, W2, B2, nullptr, 0, qo, HID, CCH);

    // ---- attention ----
    attn_kernel<<<dim3(SEQ / 128, 2 * NH), 128>>>(x);

    // ---- MLPs (3-term split bf16, fp32-quality) ----
    dim3 g1(HID / 64, NTOK / 128);
    dim3 g2(CCH / 64, NTOK / 128);
    gemm_bf16_kernel<true,  false><<<g1, 128>>>(x,   m1_w1, m1_b1, nullptr, hb,  NTOK, CCH, HID);
    gemm_bf16_kernel<false, true ><<<g2, 128>>>(hb,  m1_w2, m1_b2, vp,      rs1, NTOK, HID, CCH);
    gemm_bf16_kernel<true,  false><<<g1, 128>>>(rs1, m2_w1, m2_b1, nullptr, hb,  NTOK, CCH, HID);
    gemm_bf16_kernel<false, true ><<<g2, 128>>>(hb,  m2_w2, m2_b2, rs1,     qp,  NTOK, HID, CCH);

    out_transpose_kernel<<<dim3(SEQ / 32, CCH / 32, 2), dim3(32, 8)>>>(qp, (float*)d_out);
}

// round 10
// speedup vs baseline: 1.2759x; 1.0325x over previous
#include <cuda_runtime.h>
#include <cuda_bf16.h>
#include <cstdint>

#define NTOK 8192      // B*S
#define CCH  128       // C
#define HID  256       // 2C
#define SEQ  4096      // S per batch
#define NH   4
#define HD   32

typedef unsigned int u32;

// ---------------- scratch (static device memory, no allocs) ----------------
__device__ float g_qp [NTOK * CCH];
__device__ float g_vp [NTOK * CCH];
__device__ float g_x  [NTOK * CCH];
__device__ float g_rs1[NTOK * CCH];
__device__ float g_h  [NTOK * HID];
__device__ float g_x3 [3 * NTOK * CCH];
__device__ float g_h3 [3 * NTOK * HID];
// head-major fp16 operands: [b*NH+h][token][16 u32]
__device__ u32 g_qf[2 * NH * SEQ * 16];
__device__ u32 g_kf[2 * NH * SEQ * 16];
__device__ u32 g_vf[2 * NH * SEQ * 16];

struct Ptrs3  { const float* p[3]; };
struct LNIn   { const float* x[3]; const float* g[3]; const float* b[3]; };
struct QKVOut { u32* o16[3]; float sc[3]; float* vC; };

// ---------------- pack helpers ----------------------------------------------
__device__ __forceinline__ u32 packbf_tr(float x, float y) {   // truncation hi
    return (__float_as_uint(y) & 0xffff0000u) | (__float_as_uint(x) >> 16);
}
__device__ __forceinline__ float trhi(float x) {
    return __uint_as_float(__float_as_uint(x) & 0xffff0000u);
}
__device__ __forceinline__ u32 packbf_rn(float x, float y) {
    u32 d; asm("cvt.rn.bf16x2.f32 %0,%2,%1;" : "=r"(d) : "f"(x), "f"(y)); return d;
}
__device__ __forceinline__ u32 packhf(float x, float y) {      // fp16x2, x->low
    u32 d; asm("cvt.rn.f16x2.f32 %0,%2,%1;" : "=r"(d) : "f"(x), "f"(y)); return d;
}
__device__ __forceinline__ float exf(float x) {                // MUFU exp2
    float r; asm("ex2.approx.f32 %0,%1;" : "=f"(r) : "f"(x)); return r;
}
__device__ __forceinline__ u32 sptr(const void* p) {
    u32 a; asm("{.reg .u64 t; cvta.to.shared.u64 t,%1; cvt.u32.u64 %0,t;}" : "=r"(a) : "l"(p));
    return a;
}

// ---------------- mma / ldmatrix wrappers -----------------------------------
__device__ __forceinline__ void mma16816(float* c, const u32* a, const u32* b) {  // bf16
    asm volatile(
        "mma.sync.aligned.m16n8k16.row.col.f32.bf16.bf16.f32 "
        "{%0,%1,%2,%3},{%4,%5,%6,%7},{%8,%9},{%0,%1,%2,%3};"
        : "+f"(c[0]), "+f"(c[1]), "+f"(c[2]), "+f"(c[3])
        : "r"(a[0]), "r"(a[1]), "r"(a[2]), "r"(a[3]), "r"(b[0]), "r"(b[1]));
}
__device__ __forceinline__ void mma16816h(float* c, const u32* a, const u32* b) { // fp16
    asm volatile(
        "mma.sync.aligned.m16n8k16.row.col.f32.f16.f16.f32 "
        "{%0,%1,%2,%3},{%4,%5,%6,%7},{%8,%9},{%0,%1,%2,%3};"
        : "+f"(c[0]), "+f"(c[1]), "+f"(c[2]), "+f"(c[3])
        : "r"(a[0]), "r"(a[1]), "r"(a[2]), "r"(a[3]), "r"(b[0]), "r"(b[1]));
}
__device__ __forceinline__ void ldsm4(u32& r0, u32& r1, u32& r2, u32& r3, u32 addr) {
    asm volatile("ldmatrix.sync.aligned.m8n8.x4.shared.b16 {%0,%1,%2,%3},[%4];"
                 : "=r"(r0), "=r"(r1), "=r"(r2), "=r"(r3) : "r"(addr));
}
__device__ __forceinline__ void ldsm4t(u32& r0, u32& r1, u32& r2, u32& r3, u32 addr) {
    asm volatile("ldmatrix.sync.aligned.m8n8.x4.trans.shared.b16 {%0,%1,%2,%3},[%4];"
                 : "=r"(r0), "=r"(r1), "=r"(r2), "=r"(r3) : "r"(addr));
}

// ---------------- LayerNorm + transpose, batched over q/k/v ------------------
__global__ __launch_bounds__(256) void ln_transpose_kernel(LNIn in, float* __restrict__ y3)
{
    __shared__ float tile[CCH][17];
    const int z   = blockIdx.z;
    const float* x   = in.x[z];
    const float* gam = in.g[z];
    const float* bet = in.b[z];
    float* y = y3 + (size_t)z * NTOK * CCH;

    const int tid = threadIdx.x;
    const int s0  = blockIdx.x * 16;
    const int bb  = blockIdx.y;

    #pragma unroll
    for (int it = 0; it < 8; it++) {
        int idx = tid + it * 256;
        int c = idx >> 4, t = idx & 15;
        tile[c][t] = x[(size_t)bb * CCH * SEQ + (size_t)c * SEQ + s0 + t];
    }
    __syncthreads();

    const int w = tid >> 5, lane = tid & 31;
    #pragma unroll
    for (int rep = 0; rep < 2; rep++) {
        int t = w * 2 + rep;
        float sum = 0.f, sq = 0.f;
        #pragma unroll
        for (int j = 0; j < 4; j++) {
            float v = tile[lane + 32 * j][t];
            sum += v; sq += v * v;
        }
        #pragma unroll
        for (int off = 16; off > 0; off >>= 1) {
            sum += __shfl_xor_sync(0xffffffffu, sum, off);
            sq  += __shfl_xor_sync(0xffffffffu, sq,  off);
        }
        float mu   = sum * (1.0f / CCH);
        float var  = sq * (1.0f / CCH) - mu * mu;
        float rstd = rsqrtf(var + 1e-5f);
        size_t row = ((size_t)bb * SEQ + s0 + t) * CCH;
        #pragma unroll
        for (int j = 0; j < 4; j++) {
            int c = lane + 32 * j;
            y[row + c] = (tile[c][t] - mu) * rstd * gam[c] + bet[c];
        }
    }
}

#define AROW 12
#define BROW 36

// ---------------- single-term fp16 GEMM, batched over z (q/k/v) --------------
template <bool LEAKY, bool QKV>
__global__ __launch_bounds__(128, 2) void gemm_h1_kernel(
    const float* __restrict__ Abase, long Astride,
    Ptrs3 W, Ptrs3 Bi,
    float* __restrict__ Cbase, long Cstride,
    QKVOut qo, int K, int M)
{
    __shared__ __align__(16) u32 sA[2][128 * AROW];
    __shared__ __align__(16) u32 sB[2][16 * BROW];

    const int z = blockIdx.z;
    const float* A    = Abase + (size_t)z * Astride;
    const float* Bw   = W.p[z];
    const float* bias = Bi.p[z];

    const int tid  = threadIdx.x;
    const int lane = tid & 31;
    const int w    = tid >> 5;
    const int n0 = blockIdx.y * 128;
    const int m0 = blockIdx.x * 64;

    const int g  = lane >> 3;
    const int lr = lane & 7;

    int arow[4], acol[4];
    #pragma unroll
    for (int j = 0; j < 4; j++) {
        int idx = tid + 128 * j;
        arow[j] = idx >> 2;
        acol[j] = idx & 3;
    }
    int brow[2], bcol[2];
    #pragma unroll
    for (int j = 0; j < 2; j++) {
        int idx = tid + 128 * j;
        brow[j] = idx >> 4;
        bcol[j] = idx & 15;
    }

    float c[2][8][4];
    #pragma unroll
    for (int mi = 0; mi < 2; mi++)
        #pragma unroll
        for (int nt = 0; nt < 8; nt++)
            #pragma unroll
            for (int e = 0; e < 4; e++) c[mi][nt][e] = 0.f;

    const u32 bA0 = sptr(&sA[0][0]);
    const u32 bB0 = sptr(&sB[0][0]);
    const u32 abuf = 128 * AROW * 4;
    const u32 bbuf = 16 * BROW * 4;

    const int NT = K >> 4;

    float4 af[4], bf4[2];
    #pragma unroll
    for (int j = 0; j < 4; j++)
        af[j] = *reinterpret_cast<const float4*>(&A[(size_t)(n0 + arow[j]) * K + acol[j] * 4]);
    #pragma unroll
    for (int j = 0; j < 2; j++)
        bf4[j] = *reinterpret_cast<const float4*>(&Bw[(size_t)brow[j] * M + m0 + bcol[j] * 4]);

    #pragma unroll
    for (int j = 0; j < 4; j++) {
        int o = arow[j] * AROW + acol[j] * 2;
        sA[0][o]     = packhf(af[j].x, af[j].y);
        sA[0][o + 1] = packhf(af[j].z, af[j].w);
    }
    #pragma unroll
    for (int j = 0; j < 2; j++) {
        int o = brow[j] * BROW + bcol[j] * 2;
        sB[0][o]     = packhf(bf4[j].x, bf4[j].y);
        sB[0][o + 1] = packhf(bf4[j].z, bf4[j].w);
    }
    __syncthreads();

    for (int t = 0; t < NT; t++) {
        const int buf = t & 1;
        const u32 aS = bA0 + buf * abuf;
        const u32 bS = bB0 + buf * bbuf;

        if (t + 1 < NT) {
            int k0 = (t + 1) * 16;
            #pragma unroll
            for (int j = 0; j < 4; j++)
                af[j] = *reinterpret_cast<const float4*>(&A[(size_t)(n0 + arow[j]) * K + k0 + acol[j] * 4]);
            #pragma unroll
            for (int j = 0; j < 2; j++)
                bf4[j] = *reinterpret_cast<const float4*>(&Bw[(size_t)(k0 + brow[j]) * M + m0 + bcol[j] * 4]);
        }

        u32 aF[2][4];
        #pragma unroll
        for (int mi = 0; mi < 2; mi++) {
            u32 off = (u32)((w * 32 + mi * 16 + (g & 1) * 8 + lr) * 48 + (g >> 1) * 16);
            ldsm4(aF[mi][0], aF[mi][1], aF[mi][2], aF[mi][3], aS + off);
        }
        u32 bF[8][2];
        #pragma unroll
        for (int dp = 0; dp < 4; dp++) {
            u32 off = (u32)((8 * (g & 1) + lr) * 144 + (dp * 16 + 8 * (g >> 1)) * 2);
            ldsm4t(bF[2 * dp][0], bF[2 * dp][1], bF[2 * dp + 1][0], bF[2 * dp + 1][1], bS + off);
        }

        #pragma unroll
        for (int mi = 0; mi < 2; mi++)
            #pragma unroll
            for (int nt = 0; nt < 8; nt++)
                mma16816h(c[mi][nt], aF[mi], bF[nt]);

        if (t + 1 < NT) {
            const int nb = (t + 1) & 1;
            #pragma unroll
            for (int j = 0; j < 4; j++) {
                int o = arow[j] * AROW + acol[j] * 2;
                sA[nb][o]     = packhf(af[j].x, af[j].y);
                sA[nb][o + 1] = packhf(af[j].z, af[j].w);
            }
            #pragma unroll
            for (int j = 0; j < 2; j++) {
                int o = brow[j] * BROW + bcol[j] * 2;
                sB[nb][o]     = packhf(bf4[j].x, bf4[j].y);
                sB[nb][o + 1] = packhf(bf4[j].z, bf4[j].w);
            }
        }
        __syncthreads();
    }

    // ---- epilogue -----------------------------------------------------------
    #pragma unroll
    for (int mi = 0; mi < 2; mi++) {
        int r0 = n0 + w * 32 + mi * 16 + (lane >> 2);
        #pragma unroll
        for (int nt = 0; nt < 8; nt++) {
            int col = m0 + nt * 8 + (lane & 3) * 2;
            float2 bb = *reinterpret_cast<const float2*>(&bias[col]);
            float v0 = c[mi][nt][0] + bb.x;
            float v1 = c[mi][nt][1] + bb.y;
            float v2 = c[mi][nt][2] + bb.x;
            float v3 = c[mi][nt][3] + bb.y;
            if (LEAKY) {
                v0 = fmaxf(v0, 0.f) + 0.01f * fminf(v0, 0.f);
                v1 = fmaxf(v1, 0.f) + 0.01f * fminf(v1, 0.f);
                v2 = fmaxf(v2, 0.f) + 0.01f * fminf(v2, 0.f);
                v3 = fmaxf(v3, 0.f) + 0.01f * fminf(v3, 0.f);
            }
            if (!QKV) {
                float* C = Cbase + (size_t)z * Cstride;
                *reinterpret_cast<float2*>(&C[(size_t)r0 * M + col])       = make_float2(v0, v1);
                *reinterpret_cast<float2*>(&C[(size_t)(r0 + 8) * M + col]) = make_float2(v2, v3);
            } else {
                int h = col >> 5, dpair = (col & 31) >> 1;
                int bI = r0 >> 12, sI = r0 & (SEQ - 1);
                size_t oA = ((size_t)(bI * NH + h) * SEQ + sI) * 16 + dpair;
                size_t oB = oA + 8 * 16;
                u32* o16 = qo.o16[z];
                float sc = qo.sc[z];
                o16[oA] = packhf(v0 * sc, v1 * sc);
                o16[oB] = packhf(v2 * sc, v3 * sc);
                if (z == 2) {
                    *reinterpret_cast<float2*>(&qo.vC[(size_t)r0 * M + col])       = make_float2(v0, v1);
                    *reinterpret_cast<float2*>(&qo.vC[(size_t)(r0 + 8) * M + col]) = make_float2(v2, v3);
                }
            }
        }
    }
}

// ---------------- 3-term split-bf16 GEMM (MLP path) --------------------------
template <bool LEAKY, bool RES>
__global__ __launch_bounds__(128) void gemm_bf16_kernel(
    const float* __restrict__ A, const float* __restrict__ B,
    const float* __restrict__ bias, const float* __restrict__ res,
    float* __restrict__ C, int N, int K, int M)
{
    __shared__ __align__(16) u32 sAhi[2][128 * AROW];
    __shared__ __align__(16) u32 sAlo[2][128 * AROW];
    __shared__ __align__(16) u32 sBhi[2][16 * BROW];
    __shared__ __align__(16) u32 sBlo[2][16 * BROW];

    const int tid  = threadIdx.x;
    const int lane = tid & 31;
    const int w    = tid >> 5;
    const int n0 = blockIdx.y * 128;
    const int m0 = blockIdx.x * 64;

    const int g  = lane >> 3;
    const int lr = lane & 7;

    int arow[4], acol[4];
    #pragma unroll
    for (int j = 0; j < 4; j++) {
        int idx = tid + 128 * j;
        arow[j] = idx >> 2;
        acol[j] = idx & 3;
    }
    int brow[2], bcol[2];
    #pragma unroll
    for (int j = 0; j < 2; j++) {
        int idx = tid + 128 * j;
        brow[j] = idx >> 4;
        bcol[j] = idx & 15;
    }

    float c[2][8][4];
    #pragma unroll
    for (int mi = 0; mi < 2; mi++)
        #pragma unroll
        for (int nt = 0; nt < 8; nt++)
            #pragma unroll
            for (int e = 0; e < 4; e++) c[mi][nt][e] = 0.f;

    const u32 bA0 = sptr(&sAhi[0][0]);
    const u32 bAl0 = sptr(&sAlo[0][0]);
    const u32 bB0 = sptr(&sBhi[0][0]);
    const u32 bBl0 = sptr(&sBlo[0][0]);
    const u32 abuf = 128 * AROW * 4;
    const u32 bbuf = 16 * BROW * 4;

    const int NT = K >> 4;

    float4 af[4], bf4[2];
    #pragma unroll
    for (int j = 0; j < 4; j++)
        af[j] = *reinterpret_cast<const float4*>(&A[(size_t)(n0 + arow[j]) * K + acol[j] * 4]);
    #pragma unroll
    for (int j = 0; j < 2; j++)
        bf4[j] = *reinterpret_cast<const float4*>(&B[(size_t)brow[j] * M + m0 + bcol[j] * 4]);

    #pragma unroll
    for (int j = 0; j < 4; j++) {
        int o = arow[j] * AROW + acol[j] * 2;
        float4 f = af[j];
        sAhi[0][o]     = packbf_tr(f.x, f.y);
        sAhi[0][o + 1] = packbf_tr(f.z, f.w);
        sAlo[0][o]     = packbf_rn(f.x - trhi(f.x), f.y - trhi(f.y));
        sAlo[0][o + 1] = packbf_rn(f.z - trhi(f.z), f.w - trhi(f.w));
    }
    #pragma unroll
    for (int j = 0; j < 2; j++) {
        int o = brow[j] * BROW + bcol[j] * 2;
        float4 f = bf4[j];
        sBhi[0][o]     = packbf_tr(f.x, f.y);
        sBhi[0][o + 1] = packbf_tr(f.z, f.w);
        sBlo[0][o]     = packbf_rn(f.x - trhi(f.x), f.y - trhi(f.y));
        sBlo[0][o + 1] = packbf_rn(f.z - trhi(f.z), f.w - trhi(f.w));
    }
    __syncthreads();

    for (int t = 0; t < NT; t++) {
        const int buf = t & 1;
        const u32 aH = bA0  + buf * abuf;
        const u32 aL = bAl0 + buf * abuf;
        const u32 bH = bB0  + buf * bbuf;
        const u32 bL = bBl0 + buf * bbuf;

        if (t + 1 < NT) {
            int k0 = (t + 1) * 16;
            #pragma unroll
            for (int j = 0; j < 4; j++)
                af[j] = *reinterpret_cast<const float4*>(&A[(size_t)(n0 + arow[j]) * K + k0 + acol[j] * 4]);
            #pragma unroll
            for (int j = 0; j < 2; j++)
                bf4[j] = *reinterpret_cast<const float4*>(&B[(size_t)(k0 + brow[j]) * M + m0 + bcol[j] * 4]);
        }

        u32 ahi[2][4], alo[2][4];
        #pragma unroll
        for (int mi = 0; mi < 2; mi++) {
            u32 off = (u32)((w * 32 + mi * 16 + (g & 1) * 8 + lr) * 48 + (g >> 1) * 16);
            ldsm4(ahi[mi][0], ahi[mi][1], ahi[mi][2], ahi[mi][3], aH + off);
            ldsm4(alo[mi][0], alo[mi][1], alo[mi][2], alo[mi][3], aL + off);
        }
        u32 bhi[8][2], blo[8][2];
        #pragma unroll
        for (int dp = 0; dp < 4; dp++) {
            u32 off = (u32)((8 * (g & 1) + lr) * 144 + (dp * 16 + 8 * (g >> 1)) * 2);
            ldsm4t(bhi[2 * dp][0], bhi[2 * dp][1], bhi[2 * dp + 1][0], bhi[2 * dp + 1][1], bH + off);
            ldsm4t(blo[2 * dp][0], blo[2 * dp][1], blo[2 * dp + 1][0], blo[2 * dp + 1][1], bL + off);
        }

        #pragma unroll
        for (int mi = 0; mi < 2; mi++)
            #pragma unroll
            for (int nt = 0; nt < 8; nt++) {
                mma16816(c[mi][nt], ahi[mi], bhi[nt]);
                mma16816(c[mi][nt], ahi[mi], blo[nt]);
                mma16816(c[mi][nt], alo[mi], bhi[nt]);
            }

        if (t + 1 < NT) {
            const int nb = (t + 1) & 1;
            #pragma unroll
            for (int j = 0; j < 4; j++) {
                int o = arow[j] * AROW + acol[j] * 2;
                float4 f = af[j];
                sAhi[nb][o]     = packbf_tr(f.x, f.y);
                sAhi[nb][o + 1] = packbf_tr(f.z, f.w);
                sAlo[nb][o]     = packbf_rn(f.x - trhi(f.x), f.y - trhi(f.y));
                sAlo[nb][o + 1] = packbf_rn(f.z - trhi(f.z), f.w - trhi(f.w));
            }
            #pragma unroll
            for (int j = 0; j < 2; j++) {
                int o = brow[j] * BROW + bcol[j] * 2;
                float4 f = bf4[j];
                sBhi[nb][o]     = packbf_tr(f.x, f.y);
                sBhi[nb][o + 1] = packbf_tr(f.z, f.w);
                sBlo[nb][o]     = packbf_rn(f.x - trhi(f.x), f.y - trhi(f.y));
                sBlo[nb][o + 1] = packbf_rn(f.z - trhi(f.z), f.w - trhi(f.w));
            }
        }
        __syncthreads();
    }

    #pragma unroll
    for (int mi = 0; mi < 2; mi++) {
        int r0 = n0 + w * 32 + mi * 16 + (lane >> 2);
        #pragma unroll
        for (int nt = 0; nt < 8; nt++) {
            int col = m0 + nt * 8 + (lane & 3) * 2;
            float2 bb = *reinterpret_cast<const float2*>(&bias[col]);
            float v0 = c[mi][nt][0] + bb.x;
            float v1 = c[mi][nt][1] + bb.y;
            float v2 = c[mi][nt][2] + bb.x;
            float v3 = c[mi][nt][3] + bb.y;
            if (LEAKY) {
                v0 = fmaxf(v0, 0.f) + 0.01f * fminf(v0, 0.f);
                v1 = fmaxf(v1, 0.f) + 0.01f * fminf(v1, 0.f);
                v2 = fmaxf(v2, 0.f) + 0.01f * fminf(v2, 0.f);
                v3 = fmaxf(v3, 0.f) + 0.01f * fminf(v3, 0.f);
            }
            if (RES) {
                float2 r4a = *reinterpret_cast<const float2*>(&res[(size_t)r0 * M + col]);
                float2 r4b = *reinterpret_cast<const float2*>(&res[(size_t)(r0 + 8) * M + col]);
                v0 += r4a.x; v1 += r4a.y; v2 += r4b.x; v3 += r4b.y;
            }
            *reinterpret_cast<float2*>(&C[(size_t)r0 * M + col])       = make_float2(v0, v1);
            *reinterpret_cast<float2*>(&C[(size_t)(r0 + 8) * M + col]) = make_float2(v2, v3);
        }
    }
}

// ---------------- FA2 attention: 8 warps x 16 q-rows, fp16 -------------------
#define KVT 64
#define ROWU 20

__global__ __launch_bounds__(256, 2) void attn_kernel(float* __restrict__ xo)
{
    __shared__ __align__(16) u32 skk[2][KVT * ROWU];
    __shared__ __align__(16) u32 svv[2][KVT * ROWU];

    const int tid  = threadIdx.x;
    const int lane = tid & 31;
    const int w    = tid >> 5;                 // 0..7
    const int bh   = blockIdx.y;
    const int bb   = bh >> 2, h = bh & 3;
    const int sq0  = blockIdx.x * 128 + w * 16;

    // ---- load Q fragments (fp16, pre-scaled): one 16-row tile per warp ------
    u32 qR[2][4];
    {
        size_t qb = ((size_t)bh * SEQ + sq0 + (lane >> 2)) * 16;
        #pragma unroll
        for (int kt = 0; kt < 2; kt++) {
            int d0 = kt * 8 + (lane & 3);
            qR[kt][0] = g_qf[qb + d0];
            qR[kt][1] = g_qf[qb + 8 * 16 + d0];
            qR[kt][2] = g_qf[qb + d0 + 4];
            qR[kt][3] = g_qf[qb + 8 * 16 + d0 + 4];
        }
    }

    float o[4][4];
    #pragma unroll
    for (int dn = 0; dn < 4; dn++)
        #pragma unroll
        for (int e = 0; e < 4; e++) o[dn][e] = 0.f;
    float m0r = -1e30f, m1r = -1e30f;
    float l0r = 0.f,    l1r = 0.f;

    // staging: 1 uint4 per array per thread (256 threads cover 64 rows x 4)
    const int srow = tid >> 2;
    const int scq  = tid & 3;
    const size_t kvbase = (size_t)bh * SEQ * 16;

    const int g  = lane >> 3;
    const int lr = lane & 7;
    const u32 bK0 = sptr(&skk[0][0]);
    const u32 bV0 = sptr(&svv[0][0]);
    const u32 bufstride = KVT * ROWU * 4;

    uint4 pk, pv;
    {
        size_t go = kvbase + (size_t)srow * 16 + scq * 4;
        pk = *reinterpret_cast<const uint4*>(g_kf + go);
        pv = *reinterpret_cast<const uint4*>(g_vf + go);
    }
    {
        u32 so = srow * ROWU + scq * 4;
        *reinterpret_cast<uint4*>(&skk[0][so]) = pk;
        *reinterpret_cast<uint4*>(&svv[0][so]) = pv;
    }
    __syncthreads();

    const int NT = SEQ / KVT;
    for (int t = 0; t < NT; t++) {
        const int buf = t & 1;
        const u32 bK = bK0 + buf * bufstride;
        const u32 bV = bV0 + buf * bufstride;

        if (t + 1 < NT) {
            size_t go = kvbase + (size_t)((t + 1) * KVT + srow) * 16 + scq * 4;
            pk = *reinterpret_cast<const uint4*>(g_kf + go);
            pv = *reinterpret_cast<const uint4*>(g_vf + go);
        }

        // ---- QK^T : S[16 x 64] per warp ------------------------------------
        float s[8][4];
        #pragma unroll
        for (int nt = 0; nt < 8; nt++)
            #pragma unroll
            for (int e = 0; e < 4; e++) s[nt][e] = 0.f;

        #pragma unroll
        for (int kt = 0; kt < 2; kt++) {
            u32 bk_[8][2];
            #pragma unroll
            for (int ap = 0; ap < 4; ap++) {
                u32 off = (u32)((16 * ap + 8 * (g >> 1) + lr) * 80 + (kt * 16 + 8 * (g & 1)) * 2);
                ldsm4(bk_[2 * ap][0], bk_[2 * ap][1], bk_[2 * ap + 1][0], bk_[2 * ap + 1][1], bK + off);
            }
            #pragma unroll
            for (int nt = 0; nt < 8; nt++)
                mma16816h(s[nt], qR[kt], bk_[nt]);
        }

        // ---- online softmax --------------------------------------------------
        {
            float mx0 = -1e30f, mx1 = -1e30f;
            #pragma unroll
            for (int nt = 0; nt < 8; nt++) {
                mx0 = fmaxf(mx0, fmaxf(s[nt][0], s[nt][1]));
                mx1 = fmaxf(mx1, fmaxf(s[nt][2], s[nt][3]));
            }
            mx0 = fmaxf(mx0, __shfl_xor_sync(0xffffffffu, mx0, 1));
            mx0 = fmaxf(mx0, __shfl_xor_sync(0xffffffffu, mx0, 2));
            mx1 = fmaxf(mx1, __shfl_xor_sync(0xffffffffu, mx1, 1));
            mx1 = fmaxf(mx1, __shfl_xor_sync(0xffffffffu, mx1, 2));
            float mn0 = fmaxf(m0r, mx0);
            float mn1 = fmaxf(m1r, mx1);
            float al0 = exf(m0r - mn0);
            float al1 = exf(m1r - mn1);
            float sum0 = 0.f, sum1 = 0.f;
            #pragma unroll
            for (int nt = 0; nt < 8; nt++) {
                float p0 = exf(s[nt][0] - mn0);
                float p1 = exf(s[nt][1] - mn0);
                float p2 = exf(s[nt][2] - mn1);
                float p3 = exf(s[nt][3] - mn1);
                s[nt][0] = p0; s[nt][1] = p1;
                s[nt][2] = p2; s[nt][3] = p3;
                sum0 += p0 + p1; sum1 += p2 + p3;
            }
            sum0 += __shfl_xor_sync(0xffffffffu, sum0, 1);
            sum0 += __shfl_xor_sync(0xffffffffu, sum0, 2);
            sum1 += __shfl_xor_sync(0xffffffffu, sum1, 1);
            sum1 += __shfl_xor_sync(0xffffffffu, sum1, 2);
            l0r = l0r * al0 + sum0;
            l1r = l1r * al1 + sum1;
            m0r = mn0; m1r = mn1;
            #pragma unroll
            for (int dn = 0; dn < 4; dn++) {
                o[dn][0] *= al0; o[dn][1] *= al0;
                o[dn][2] *= al1; o[dn][3] *= al1;
            }
        }

        // ---- P @ V -----------------------------------------------------------
        #pragma unroll
        for (int kt = 0; kt < 4; kt++) {
            u32 bv[4][2];
            #pragma unroll
            for (int dp = 0; dp < 2; dp++) {
                u32 off = (u32)((16 * kt + 8 * (g & 1) + lr) * 80 + (dp * 16 + 8 * (g >> 1)) * 2);
                ldsm4t(bv[2 * dp][0], bv[2 * dp][1], bv[2 * dp + 1][0], bv[2 * dp + 1][1], bV + off);
            }
            u32 pa[4];
            pa[0] = packhf(s[2 * kt][0],     s[2 * kt][1]);
            pa[1] = packhf(s[2 * kt][2],     s[2 * kt][3]);
            pa[2] = packhf(s[2 * kt + 1][0], s[2 * kt + 1][1]);
            pa[3] = packhf(s[2 * kt + 1][2], s[2 * kt + 1][3]);
            #pragma unroll
            for (int dn = 0; dn < 4; dn++)
                mma16816h(o[dn], pa, bv[dn]);
        }

        if (t + 1 < NT) {
            const int nb = (t + 1) & 1;
            u32 so = srow * ROWU + scq * 4;
            *reinterpret_cast<uint4*>(&skk[nb][so]) = pk;
            *reinterpret_cast<uint4*>(&svv[nb][so]) = pv;
        }
        __syncthreads();
    }

    // ---- finalize & write ----------------------------------------------------
    {
        float inv0 = 1.0f / l0r;
        float inv1 = 1.0f / l1r;
        int r = bb * SEQ + sq0 + (lane >> 2);
        #pragma unroll
        for (int dn = 0; dn < 4; dn++) {
            int cc = h * HD + dn * 8 + 2 * (lane & 3);
            float2 o0 = {o[dn][0] * inv0, o[dn][1] * inv0};
            float2 o1 = {o[dn][2] * inv1, o[dn][3] * inv1};
            *reinterpret_cast<float2*>(xo + (size_t)r * CCH + cc)       = o0;
            *reinterpret_cast<float2*>(xo + (size_t)(r + 8) * CCH + cc) = o1;
        }
    }
}

// ---------------- [B*S, C] -> [B, C, S] output transpose -------------------
__global__ __launch_bounds__(256) void out_transpose_kernel(
    const float* __restrict__ src, float* __restrict__ dst)
{
    __shared__ float t[32][33];
    const int tx = threadIdx.x, ty = threadIdx.y;
    const int s0 = blockIdx.x * 32;
    const int c0 = blockIdx.y * 32;
    const int bb = blockIdx.z;
    #pragma unroll
    for (int i = ty; i < 32; i += 8)
        t[i][tx] = src[((size_t)bb * SEQ + s0 + i) * CCH + c0 + tx];
    __syncthreads();
    #pragma unroll
    for (int i = ty; i < 32; i += 8)
        dst[(size_t)bb * CCH * SEQ + (size_t)(c0 + i) * SEQ + s0 + tx] = t[tx][i];
}

// ---------------- launch ----------------------------------------------------
static float* symf(const void* symbol) {
    void* p = nullptr;
    cudaGetSymbolAddress(&p, symbol);
    return reinterpret_cast<float*>(p);
}
static u32* symu(const void* symbol) {
    void* p = nullptr;
    cudaGetSymbolAddress(&p, symbol);
    return reinterpret_cast<u32*>(p);
}

extern "C" void kernel_launch(void* const* d_in, const int* in_sizes, int n_in,
                              void* d_out, int out_size)
{
    const float* q = (const float*)d_in[0];
    const float* k = (const float*)d_in[1];
    const float* v = (const float*)d_in[2];
    const float* ln_g[3]  = {(const float*)d_in[3],  (const float*)d_in[9],  (const float*)d_in[15]};
    const float* ln_b[3]  = {(const float*)d_in[4],  (const float*)d_in[10], (const float*)d_in[16]};
    const float* w1[3]    = {(const float*)d_in[5],  (const float*)d_in[11], (const float*)d_in[17]};
    const float* b1[3]    = {(const float*)d_in[6],  (const float*)d_in[12], (const float*)d_in[18]};
    const float* w2[3]    = {(const float*)d_in[7],  (const float*)d_in[13], (const float*)d_in[19]};
    const float* b2[3]    = {(const float*)d_in[8],  (const float*)d_in[14], (const float*)d_in[20]};
    const float* m1_w1 = (const float*)d_in[21];
    const float* m1_b1 = (const float*)d_in[22];
    const float* m1_w2 = (const float*)d_in[23];
    const float* m1_b2 = (const float*)d_in[24];
    const float* m2_w1 = (const float*)d_in[25];
    const float* m2_b1 = (const float*)d_in[26];
    const float* m2_w2 = (const float*)d_in[27];
    const float* m2_b2 = (const float*)d_in[28];

    float* qp  = symf(g_qp);
    float* vp  = symf(g_vp);
    float* x   = symf(g_x);
    float* rs1 = symf(g_rs1);
    float* hb  = symf(g_h);
    float* x3  = symf(g_x3);
    float* h3  = symf(g_h3);
    u32* qf = symu(g_qf);
    u32* kf = symu(g_kf);
    u32* vf = symu(g_vf);

    const float qsc = 1.44269504088896f / 5.65685424949238f;  // log2e/sqrt(32)

    // ---- batched LN for q,k,v ----
    LNIn lp;
    lp.x[0] = q; lp.x[1] = k; lp.x[2] = v;
    for (int i = 0; i < 3; i++) { lp.g[i] = ln_g[i]; lp.b[i] = ln_b[i]; }
    ln_transpose_kernel<<<dim3(SEQ / 16, 2, 3), 256>>>(lp, x3);

    // ---- batched GEMM1 (C->2C, LeakyReLU) ----
    Ptrs3 W1 = {{w1[0], w1[1], w1[2]}};
    Ptrs3 B1 = {{b1[0], b1[1], b1[2]}};
    QKVOut dummy = {{nullptr, nullptr, nullptr}, {0.f, 0.f, 0.f}, nullptr};
    gemm_h1_kernel<true, false><<<dim3(HID / 64, NTOK / 128, 3), 128>>>(
        x3, (long)NTOK * CCH, W1, B1, h3, (long)NTOK * HID, dummy, CCH, HID);

    // ---- batched GEMM2 (2C->C, fp16 head-major out; v also fp32) ----
    Ptrs3 W2 = {{w2[0], w2[1], w2[2]}};
    Ptrs3 B2 = {{b2[0], b2[1], b2[2]}};
    QKVOut qo = {{qf, kf, vf}, {qsc, 1.f, 1.f}, vp};
    gemm_h1_kernel<false, true><<<dim3(CCH / 64, NTOK / 128, 3), 128>>>(
        h3, (long)NTOK * HID, W2, B2, nullptr, 0, qo, HID, CCH);

    // ---- attention (8 warps x 16 rows) ----
    attn_kernel<<<dim3(SEQ / 128, 2 * NH), 256>>>(x);

    // ---- MLPs (3-term split bf16, fp32-quality) ----
    dim3 g1(HID / 64, NTOK / 128);
    dim3 g2(CCH / 64, NTOK / 128);
    gemm_bf16_kernel<true,  false><<<g1, 128>>>(x,   m1_w1, m1_b1, nullptr, hb,  NTOK, CCH, HID);
    gemm_bf16_kernel<false, true ><<<g2, 128>>>(hb,  m1_w2, m1_b2, vp,      rs1, NTOK, HID, CCH);
    gemm_bf16_kernel<true,  false><<<g1, 128>>>(rs1, m2_w1, m2_b1, nullptr, hb,  NTOK, CCH, HID);
    gemm_bf16_kernel<false, true ><<<g2, 128>>>(hb,  m2_w2, m2_b2, rs1,     qp,  NTOK, HID, CCH);

    out_transpose_kernel<<<dim3(SEQ / 32, CCH / 32, 2), dim3(32, 8)>>>(qp, (float*)d_out);
}

// round 11
// speedup vs baseline: 1.4136x; 1.1079x over previous
#include <cuda_runtime.h>
#include <cuda_bf16.h>
#include <cstdint>

#define NTOK 8192      // B*S
#define CCH  128       // C
#define HID  256       // 2C
#define SEQ  4096      // S per batch
#define NH   4
#define HD   32

typedef unsigned int u32;

// ---------------- scratch (static device memory, no allocs) ----------------
__device__ float g_qp [NTOK * CCH];
__device__ float g_vp [NTOK * CCH];
__device__ float g_x  [NTOK * CCH];
__device__ float g_rs1[NTOK * CCH];
__device__ float g_h  [NTOK * HID];
__device__ float g_x3 [3 * NTOK * CCH];
__device__ float g_h3 [3 * NTOK * HID];
// head-major fp16 operands: [b*NH+h][token][16 u32]
__device__ u32 g_qf[2 * NH * SEQ * 16];
__device__ u32 g_kf[2 * NH * SEQ * 16];
__device__ u32 g_vf[2 * NH * SEQ * 16];

struct Ptrs3  { const float* p[3]; };
struct LNIn   { const float* x[3]; const float* g[3]; const float* b[3]; };
struct QKVOut { u32* o16[3]; float sc[3]; float* vC; };

// ---------------- pack helpers ----------------------------------------------
__device__ __forceinline__ u32 packbf_tr(float x, float y) {   // truncation hi
    return (__float_as_uint(y) & 0xffff0000u) | (__float_as_uint(x) >> 16);
}
__device__ __forceinline__ float trhi(float x) {
    return __uint_as_float(__float_as_uint(x) & 0xffff0000u);
}
__device__ __forceinline__ u32 packbf_rn(float x, float y) {
    u32 d; asm("cvt.rn.bf16x2.f32 %0,%2,%1;" : "=r"(d) : "f"(x), "f"(y)); return d;
}
__device__ __forceinline__ u32 packhf(float x, float y) {      // fp16x2, x->low
    u32 d; asm("cvt.rn.f16x2.f32 %0,%2,%1;" : "=r"(d) : "f"(x), "f"(y)); return d;
}
__device__ __forceinline__ float exf(float x) {                // MUFU exp2
    float r; asm("ex2.approx.f32 %0,%1;" : "=f"(r) : "f"(x)); return r;
}
__device__ __forceinline__ u32 sptr(const void* p) {
    u32 a; asm("{.reg .u64 t; cvta.to.shared.u64 t,%1; cvt.u32.u64 %0,t;}" : "=r"(a) : "l"(p));
    return a;
}

// ---------------- mma / ldmatrix wrappers -----------------------------------
__device__ __forceinline__ void mma16816(float* c, const u32* a, const u32* b) {  // bf16
    asm volatile(
        "mma.sync.aligned.m16n8k16.row.col.f32.bf16.bf16.f32 "
        "{%0,%1,%2,%3},{%4,%5,%6,%7},{%8,%9},{%0,%1,%2,%3};"
        : "+f"(c[0]), "+f"(c[1]), "+f"(c[2]), "+f"(c[3])
        : "r"(a[0]), "r"(a[1]), "r"(a[2]), "r"(a[3]), "r"(b[0]), "r"(b[1]));
}
__device__ __forceinline__ void mma16816h(float* c, const u32* a, const u32* b) { // fp16
    asm volatile(
        "mma.sync.aligned.m16n8k16.row.col.f32.f16.f16.f32 "
        "{%0,%1,%2,%3},{%4,%5,%6,%7},{%8,%9},{%0,%1,%2,%3};"
        : "+f"(c[0]), "+f"(c[1]), "+f"(c[2]), "+f"(c[3])
        : "r"(a[0]), "r"(a[1]), "r"(a[2]), "r"(a[3]), "r"(b[0]), "r"(b[1]));
}
__device__ __forceinline__ void ldsm4(u32& r0, u32& r1, u32& r2, u32& r3, u32 addr) {
    asm volatile("ldmatrix.sync.aligned.m8n8.x4.shared.b16 {%0,%1,%2,%3},[%4];"
                 : "=r"(r0), "=r"(r1), "=r"(r2), "=r"(r3) : "r"(addr));
}
__device__ __forceinline__ void ldsm4t(u32& r0, u32& r1, u32& r2, u32& r3, u32 addr) {
    asm volatile("ldmatrix.sync.aligned.m8n8.x4.trans.shared.b16 {%0,%1,%2,%3},[%4];"
                 : "=r"(r0), "=r"(r1), "=r"(r2), "=r"(r3) : "r"(addr));
}

// ---------------- LayerNorm + transpose, batched over q/k/v ------------------
__global__ __launch_bounds__(256) void ln_transpose_kernel(LNIn in, float* __restrict__ y3)
{
    __shared__ float tile[CCH][17];
    const int z   = blockIdx.z;
    const float* x   = in.x[z];
    const float* gam = in.g[z];
    const float* bet = in.b[z];
    float* y = y3 + (size_t)z * NTOK * CCH;

    const int tid = threadIdx.x;
    const int s0  = blockIdx.x * 16;
    const int bb  = blockIdx.y;

    #pragma unroll
    for (int it = 0; it < 8; it++) {
        int idx = tid + it * 256;
        int c = idx >> 4, t = idx & 15;
        tile[c][t] = x[(size_t)bb * CCH * SEQ + (size_t)c * SEQ + s0 + t];
    }
    __syncthreads();

    const int w = tid >> 5, lane = tid & 31;
    #pragma unroll
    for (int rep = 0; rep < 2; rep++) {
        int t = w * 2 + rep;
        float sum = 0.f, sq = 0.f;
        #pragma unroll
        for (int j = 0; j < 4; j++) {
            float v = tile[lane + 32 * j][t];
            sum += v; sq += v * v;
        }
        #pragma unroll
        for (int off = 16; off > 0; off >>= 1) {
            sum += __shfl_xor_sync(0xffffffffu, sum, off);
            sq  += __shfl_xor_sync(0xffffffffu, sq,  off);
        }
        float mu   = sum * (1.0f / CCH);
        float var  = sq * (1.0f / CCH) - mu * mu;
        float rstd = rsqrtf(var + 1e-5f);
        size_t row = ((size_t)bb * SEQ + s0 + t) * CCH;
        #pragma unroll
        for (int j = 0; j < 4; j++) {
            int c = lane + 32 * j;
            y[row + c] = (tile[c][t] - mu) * rstd * gam[c] + bet[c];
        }
    }
}

#define AROW 12
#define BROW 36

// ---------------- single-term fp16 GEMM, batched over z (q/k/v) --------------
template <bool LEAKY, bool QKV>
__global__ __launch_bounds__(128, 2) void gemm_h1_kernel(
    const float* __restrict__ Abase, long Astride,
    Ptrs3 W, Ptrs3 Bi,
    float* __restrict__ Cbase, long Cstride,
    QKVOut qo, int K, int M)
{
    __shared__ __align__(16) u32 sA[2][128 * AROW];
    __shared__ __align__(16) u32 sB[2][16 * BROW];

    const int z = blockIdx.z;
    const float* A    = Abase + (size_t)z * Astride;
    const float* Bw   = W.p[z];
    const float* bias = Bi.p[z];

    const int tid  = threadIdx.x;
    const int lane = tid & 31;
    const int w    = tid >> 5;
    const int n0 = blockIdx.y * 128;
    const int m0 = blockIdx.x * 64;

    const int g  = lane >> 3;
    const int lr = lane & 7;

    int arow[4], acol[4];
    #pragma unroll
    for (int j = 0; j < 4; j++) {
        int idx = tid + 128 * j;
        arow[j] = idx >> 2;
        acol[j] = idx & 3;
    }
    int brow[2], bcol[2];
    #pragma unroll
    for (int j = 0; j < 2; j++) {
        int idx = tid + 128 * j;
        brow[j] = idx >> 4;
        bcol[j] = idx & 15;
    }

    float c[2][8][4];
    #pragma unroll
    for (int mi = 0; mi < 2; mi++)
        #pragma unroll
        for (int nt = 0; nt < 8; nt++)
            #pragma unroll
            for (int e = 0; e < 4; e++) c[mi][nt][e] = 0.f;

    const u32 bA0 = sptr(&sA[0][0]);
    const u32 bB0 = sptr(&sB[0][0]);
    const u32 abuf = 128 * AROW * 4;
    const u32 bbuf = 16 * BROW * 4;

    const int NT = K >> 4;

    float4 af[4], bf4[2];
    #pragma unroll
    for (int j = 0; j < 4; j++)
        af[j] = *reinterpret_cast<const float4*>(&A[(size_t)(n0 + arow[j]) * K + acol[j] * 4]);
    #pragma unroll
    for (int j = 0; j < 2; j++)
        bf4[j] = *reinterpret_cast<const float4*>(&Bw[(size_t)brow[j] * M + m0 + bcol[j] * 4]);

    #pragma unroll
    for (int j = 0; j < 4; j++) {
        int o = arow[j] * AROW + acol[j] * 2;
        sA[0][o]     = packhf(af[j].x, af[j].y);
        sA[0][o + 1] = packhf(af[j].z, af[j].w);
    }
    #pragma unroll
    for (int j = 0; j < 2; j++) {
        int o = brow[j] * BROW + bcol[j] * 2;
        sB[0][o]     = packhf(bf4[j].x, bf4[j].y);
        sB[0][o + 1] = packhf(bf4[j].z, bf4[j].w);
    }
    __syncthreads();

    for (int t = 0; t < NT; t++) {
        const int buf = t & 1;
        const u32 aS = bA0 + buf * abuf;
        const u32 bS = bB0 + buf * bbuf;

        if (t + 1 < NT) {
            int k0 = (t + 1) * 16;
            #pragma unroll
            for (int j = 0; j < 4; j++)
                af[j] = *reinterpret_cast<const float4*>(&A[(size_t)(n0 + arow[j]) * K + k0 + acol[j] * 4]);
            #pragma unroll
            for (int j = 0; j < 2; j++)
                bf4[j] = *reinterpret_cast<const float4*>(&Bw[(size_t)(k0 + brow[j]) * M + m0 + bcol[j] * 4]);
        }

        u32 aF[2][4];
        #pragma unroll
        for (int mi = 0; mi < 2; mi++) {
            u32 off = (u32)((w * 32 + mi * 16 + (g & 1) * 8 + lr) * 48 + (g >> 1) * 16);
            ldsm4(aF[mi][0], aF[mi][1], aF[mi][2], aF[mi][3], aS + off);
        }
        u32 bF[8][2];
        #pragma unroll
        for (int dp = 0; dp < 4; dp++) {
            u32 off = (u32)((8 * (g & 1) + lr) * 144 + (dp * 16 + 8 * (g >> 1)) * 2);
            ldsm4t(bF[2 * dp][0], bF[2 * dp][1], bF[2 * dp + 1][0], bF[2 * dp + 1][1], bS + off);
        }

        #pragma unroll
        for (int mi = 0; mi < 2; mi++)
            #pragma unroll
            for (int nt = 0; nt < 8; nt++)
                mma16816h(c[mi][nt], aF[mi], bF[nt]);

        if (t + 1 < NT) {
            const int nb = (t + 1) & 1;
            #pragma unroll
            for (int j = 0; j < 4; j++) {
                int o = arow[j] * AROW + acol[j] * 2;
                sA[nb][o]     = packhf(af[j].x, af[j].y);
                sA[nb][o + 1] = packhf(af[j].z, af[j].w);
            }
            #pragma unroll
            for (int j = 0; j < 2; j++) {
                int o = brow[j] * BROW + bcol[j] * 2;
                sB[nb][o]     = packhf(bf4[j].x, bf4[j].y);
                sB[nb][o + 1] = packhf(bf4[j].z, bf4[j].w);
            }
        }
        __syncthreads();
    }

    // ---- epilogue -----------------------------------------------------------
    #pragma unroll
    for (int mi = 0; mi < 2; mi++) {
        int r0 = n0 + w * 32 + mi * 16 + (lane >> 2);
        #pragma unroll
        for (int nt = 0; nt < 8; nt++) {
            int col = m0 + nt * 8 + (lane & 3) * 2;
            float2 bb = *reinterpret_cast<const float2*>(&bias[col]);
            float v0 = c[mi][nt][0] + bb.x;
            float v1 = c[mi][nt][1] + bb.y;
            float v2 = c[mi][nt][2] + bb.x;
            float v3 = c[mi][nt][3] + bb.y;
            if (LEAKY) {
                v0 = fmaxf(v0, 0.f) + 0.01f * fminf(v0, 0.f);
                v1 = fmaxf(v1, 0.f) + 0.01f * fminf(v1, 0.f);
                v2 = fmaxf(v2, 0.f) + 0.01f * fminf(v2, 0.f);
                v3 = fmaxf(v3, 0.f) + 0.01f * fminf(v3, 0.f);
            }
            if (!QKV) {
                float* C = Cbase + (size_t)z * Cstride;
                *reinterpret_cast<float2*>(&C[(size_t)r0 * M + col])       = make_float2(v0, v1);
                *reinterpret_cast<float2*>(&C[(size_t)(r0 + 8) * M + col]) = make_float2(v2, v3);
            } else {
                int h = col >> 5, dpair = (col & 31) >> 1;
                int bI = r0 >> 12, sI = r0 & (SEQ - 1);
                size_t oA = ((size_t)(bI * NH + h) * SEQ + sI) * 16 + dpair;
                size_t oB = oA + 8 * 16;
                u32* o16 = qo.o16[z];
                float sc = qo.sc[z];
                o16[oA] = packhf(v0 * sc, v1 * sc);
                o16[oB] = packhf(v2 * sc, v3 * sc);
                if (z == 2) {
                    *reinterpret_cast<float2*>(&qo.vC[(size_t)r0 * M + col])       = make_float2(v0, v1);
                    *reinterpret_cast<float2*>(&qo.vC[(size_t)(r0 + 8) * M + col]) = make_float2(v2, v3);
                }
            }
        }
    }
}

// ---------------- 3-term split-bf16 GEMM (MLP path) --------------------------
template <bool LEAKY, bool RES>
__global__ __launch_bounds__(128) void gemm_bf16_kernel(
    const float* __restrict__ A, const float* __restrict__ B,
    const float* __restrict__ bias, const float* __restrict__ res,
    float* __restrict__ C, int N, int K, int M)
{
    __shared__ __align__(16) u32 sAhi[2][128 * AROW];
    __shared__ __align__(16) u32 sAlo[2][128 * AROW];
    __shared__ __align__(16) u32 sBhi[2][16 * BROW];
    __shared__ __align__(16) u32 sBlo[2][16 * BROW];

    const int tid  = threadIdx.x;
    const int lane = tid & 31;
    const int w    = tid >> 5;
    const int n0 = blockIdx.y * 128;
    const int m0 = blockIdx.x * 64;

    const int g  = lane >> 3;
    const int lr = lane & 7;

    int arow[4], acol[4];
    #pragma unroll
    for (int j = 0; j < 4; j++) {
        int idx = tid + 128 * j;
        arow[j] = idx >> 2;
        acol[j] = idx & 3;
    }
    int brow[2], bcol[2];
    #pragma unroll
    for (int j = 0; j < 2; j++) {
        int idx = tid + 128 * j;
        brow[j] = idx >> 4;
        bcol[j] = idx & 15;
    }

    float c[2][8][4];
    #pragma unroll
    for (int mi = 0; mi < 2; mi++)
        #pragma unroll
        for (int nt = 0; nt < 8; nt++)
            #pragma unroll
            for (int e = 0; e < 4; e++) c[mi][nt][e] = 0.f;

    const u32 bA0 = sptr(&sAhi[0][0]);
    const u32 bAl0 = sptr(&sAlo[0][0]);
    const u32 bB0 = sptr(&sBhi[0][0]);
    const u32 bBl0 = sptr(&sBlo[0][0]);
    const u32 abuf = 128 * AROW * 4;
    const u32 bbuf = 16 * BROW * 4;

    const int NT = K >> 4;

    float4 af[4], bf4[2];
    #pragma unroll
    for (int j = 0; j < 4; j++)
        af[j] = *reinterpret_cast<const float4*>(&A[(size_t)(n0 + arow[j]) * K + acol[j] * 4]);
    #pragma unroll
    for (int j = 0; j < 2; j++)
        bf4[j] = *reinterpret_cast<const float4*>(&B[(size_t)brow[j] * M + m0 + bcol[j] * 4]);

    #pragma unroll
    for (int j = 0; j < 4; j++) {
        int o = arow[j] * AROW + acol[j] * 2;
        float4 f = af[j];
        sAhi[0][o]     = packbf_tr(f.x, f.y);
        sAhi[0][o + 1] = packbf_tr(f.z, f.w);
        sAlo[0][o]     = packbf_rn(f.x - trhi(f.x), f.y - trhi(f.y));
        sAlo[0][o + 1] = packbf_rn(f.z - trhi(f.z), f.w - trhi(f.w));
    }
    #pragma unroll
    for (int j = 0; j < 2; j++) {
        int o = brow[j] * BROW + bcol[j] * 2;
        float4 f = bf4[j];
        sBhi[0][o]     = packbf_tr(f.x, f.y);
        sBhi[0][o + 1] = packbf_tr(f.z, f.w);
        sBlo[0][o]     = packbf_rn(f.x - trhi(f.x), f.y - trhi(f.y));
        sBlo[0][o + 1] = packbf_rn(f.z - trhi(f.z), f.w - trhi(f.w));
    }
    __syncthreads();

    for (int t = 0; t < NT; t++) {
        const int buf = t & 1;
        const u32 aH = bA0  + buf * abuf;
        const u32 aL = bAl0 + buf * abuf;
        const u32 bH = bB0  + buf * bbuf;
        const u32 bL = bBl0 + buf * bbuf;

        if (t + 1 < NT) {
            int k0 = (t + 1) * 16;
            #pragma unroll
            for (int j = 0; j < 4; j++)
                af[j] = *reinterpret_cast<const float4*>(&A[(size_t)(n0 + arow[j]) * K + k0 + acol[j] * 4]);
            #pragma unroll
            for (int j = 0; j < 2; j++)
                bf4[j] = *reinterpret_cast<const float4*>(&B[(size_t)(k0 + brow[j]) * M + m0 + bcol[j] * 4]);
        }

        u32 ahi[2][4], alo[2][4];
        #pragma unroll
        for (int mi = 0; mi < 2; mi++) {
            u32 off = (u32)((w * 32 + mi * 16 + (g & 1) * 8 + lr) * 48 + (g >> 1) * 16);
            ldsm4(ahi[mi][0], ahi[mi][1], ahi[mi][2], ahi[mi][3], aH + off);
            ldsm4(alo[mi][0], alo[mi][1], alo[mi][2], alo[mi][3], aL + off);
        }
        u32 bhi[8][2], blo[8][2];
        #pragma unroll
        for (int dp = 0; dp < 4; dp++) {
            u32 off = (u32)((8 * (g & 1) + lr) * 144 + (dp * 16 + 8 * (g >> 1)) * 2);
            ldsm4t(bhi[2 * dp][0], bhi[2 * dp][1], bhi[2 * dp + 1][0], bhi[2 * dp + 1][1], bH + off);
            ldsm4t(blo[2 * dp][0], blo[2 * dp][1], blo[2 * dp + 1][0], blo[2 * dp + 1][1], bL + off);
        }

        #pragma unroll
        for (int mi = 0; mi < 2; mi++)
            #pragma unroll
            for (int nt = 0; nt < 8; nt++) {
                mma16816(c[mi][nt], ahi[mi], bhi[nt]);
                mma16816(c[mi][nt], ahi[mi], blo[nt]);
                mma16816(c[mi][nt], alo[mi], bhi[nt]);
            }

        if (t + 1 < NT) {
            const int nb = (t + 1) & 1;
            #pragma unroll
            for (int j = 0; j < 4; j++) {
                int o = arow[j] * AROW + acol[j] * 2;
                float4 f = af[j];
                sAhi[nb][o]     = packbf_tr(f.x, f.y);
                sAhi[nb][o + 1] = packbf_tr(f.z, f.w);
                sAlo[nb][o]     = packbf_rn(f.x - trhi(f.x), f.y - trhi(f.y));
                sAlo[nb][o + 1] = packbf_rn(f.z - trhi(f.z), f.w - trhi(f.w));
            }
            #pragma unroll
            for (int j = 0; j < 2; j++) {
                int o = brow[j] * BROW + bcol[j] * 2;
                float4 f = bf4[j];
                sBhi[nb][o]     = packbf_tr(f.x, f.y);
                sBhi[nb][o + 1] = packbf_tr(f.z, f.w);
                sBlo[nb][o]     = packbf_rn(f.x - trhi(f.x), f.y - trhi(f.y));
                sBlo[nb][o + 1] = packbf_rn(f.z - trhi(f.z), f.w - trhi(f.w));
            }
        }
        __syncthreads();
    }

    #pragma unroll
    for (int mi = 0; mi < 2; mi++) {
        int r0 = n0 + w * 32 + mi * 16 + (lane >> 2);
        #pragma unroll
        for (int nt = 0; nt < 8; nt++) {
            int col = m0 + nt * 8 + (lane & 3) * 2;
            float2 bb = *reinterpret_cast<const float2*>(&bias[col]);
            float v0 = c[mi][nt][0] + bb.x;
            float v1 = c[mi][nt][1] + bb.y;
            float v2 = c[mi][nt][2] + bb.x;
            float v3 = c[mi][nt][3] + bb.y;
            if (LEAKY) {
                v0 = fmaxf(v0, 0.f) + 0.01f * fminf(v0, 0.f);
                v1 = fmaxf(v1, 0.f) + 0.01f * fminf(v1, 0.f);
                v2 = fmaxf(v2, 0.f) + 0.01f * fminf(v2, 0.f);
                v3 = fmaxf(v3, 0.f) + 0.01f * fminf(v3, 0.f);
            }
            if (RES) {
                float2 r4a = *reinterpret_cast<const float2*>(&res[(size_t)r0 * M + col]);
                float2 r4b = *reinterpret_cast<const float2*>(&res[(size_t)(r0 + 8) * M + col]);
                v0 += r4a.x; v1 += r4a.y; v2 += r4b.x; v3 += r4b.y;
            }
            *reinterpret_cast<float2*>(&C[(size_t)r0 * M + col])       = make_float2(v0, v1);
            *reinterpret_cast<float2*>(&C[(size_t)(r0 + 8) * M + col]) = make_float2(v2, v3);
        }
    }
}

// ---------------- FA attention: unnormalized exp2 (bounded logits) -----------
// 8 warps x 16 q-rows; no online max (logits provably < ~16 in exp2 units),
// l reduced across lane-quad only once at the end.
#define KVT 64
#define ROWU 20

__global__ __launch_bounds__(256, 2) void attn_kernel(float* __restrict__ xo)
{
    __shared__ __align__(16) u32 skk[2][KVT * ROWU];
    __shared__ __align__(16) u32 svv[2][KVT * ROWU];

    const int tid  = threadIdx.x;
    const int lane = tid & 31;
    const int w    = tid >> 5;                 // 0..7
    const int bh   = blockIdx.y;
    const int bb   = bh >> 2, h = bh & 3;
    const int sq0  = blockIdx.x * 128 + w * 16;

    // ---- load Q fragments (fp16, pre-scaled): one 16-row tile per warp ------
    u32 qR[2][4];
    {
        size_t qb = ((size_t)bh * SEQ + sq0 + (lane >> 2)) * 16;
        #pragma unroll
        for (int kt = 0; kt < 2; kt++) {
            int d0 = kt * 8 + (lane & 3);
            qR[kt][0] = g_qf[qb + d0];
            qR[kt][1] = g_qf[qb + 8 * 16 + d0];
            qR[kt][2] = g_qf[qb + d0 + 4];
            qR[kt][3] = g_qf[qb + 8 * 16 + d0 + 4];
        }
    }

    float o[4][4];
    #pragma unroll
    for (int dn = 0; dn < 4; dn++)
        #pragma unroll
        for (int e = 0; e < 4; e++) o[dn][e] = 0.f;
    float l0r = 0.f, l1r = 0.f;    // per-thread partial sums (quad-reduced at end)

    const int srow = tid >> 2;
    const int scq  = tid & 3;
    const size_t kvbase = (size_t)bh * SEQ * 16;

    const int g  = lane >> 3;
    const int lr = lane & 7;
    const u32 bK0 = sptr(&skk[0][0]);
    const u32 bV0 = sptr(&svv[0][0]);
    const u32 bufstride = KVT * ROWU * 4;

    uint4 pk, pv;
    {
        size_t go = kvbase + (size_t)srow * 16 + scq * 4;
        pk = *reinterpret_cast<const uint4*>(g_kf + go);
        pv = *reinterpret_cast<const uint4*>(g_vf + go);
    }
    {
        u32 so = srow * ROWU + scq * 4;
        *reinterpret_cast<uint4*>(&skk[0][so]) = pk;
        *reinterpret_cast<uint4*>(&svv[0][so]) = pv;
    }
    __syncthreads();

    const int NT = SEQ / KVT;
    for (int t = 0; t < NT; t++) {
        const int buf = t & 1;
        const u32 bK = bK0 + buf * bufstride;
        const u32 bV = bV0 + buf * bufstride;

        if (t + 1 < NT) {
            size_t go = kvbase + (size_t)((t + 1) * KVT + srow) * 16 + scq * 4;
            pk = *reinterpret_cast<const uint4*>(g_kf + go);
            pv = *reinterpret_cast<const uint4*>(g_vf + go);
        }

        // ---- QK^T : S[16 x 64] per warp ------------------------------------
        float s[8][4];
        #pragma unroll
        for (int nt = 0; nt < 8; nt++)
            #pragma unroll
            for (int e = 0; e < 4; e++) s[nt][e] = 0.f;

        #pragma unroll
        for (int kt = 0; kt < 2; kt++) {
            u32 bk_[8][2];
            #pragma unroll
            for (int ap = 0; ap < 4; ap++) {
                u32 off = (u32)((16 * ap + 8 * (g >> 1) + lr) * 80 + (kt * 16 + 8 * (g & 1)) * 2);
                ldsm4(bk_[2 * ap][0], bk_[2 * ap][1], bk_[2 * ap + 1][0], bk_[2 * ap + 1][1], bK + off);
            }
            #pragma unroll
            for (int nt = 0; nt < 8; nt++)
                mma16816h(s[nt], qR[kt], bk_[nt]);
        }

        // ---- unnormalized exp (no max, no rescale) ---------------------------
        #pragma unroll
        for (int nt = 0; nt < 8; nt++) {
            float p0 = exf(s[nt][0]);
            float p1 = exf(s[nt][1]);
            float p2 = exf(s[nt][2]);
            float p3 = exf(s[nt][3]);
            s[nt][0] = p0; s[nt][1] = p1;
            s[nt][2] = p2; s[nt][3] = p3;
            l0r += p0 + p1;
            l1r += p2 + p3;
        }

        // ---- P @ V -----------------------------------------------------------
        #pragma unroll
        for (int kt = 0; kt < 4; kt++) {
            u32 bv[4][2];
            #pragma unroll
            for (int dp = 0; dp < 2; dp++) {
                u32 off = (u32)((16 * kt + 8 * (g & 1) + lr) * 80 + (dp * 16 + 8 * (g >> 1)) * 2);
                ldsm4t(bv[2 * dp][0], bv[2 * dp][1], bv[2 * dp + 1][0], bv[2 * dp + 1][1], bV + off);
            }
            u32 pa[4];
            pa[0] = packhf(s[2 * kt][0],     s[2 * kt][1]);
            pa[1] = packhf(s[2 * kt][2],     s[2 * kt][3]);
            pa[2] = packhf(s[2 * kt + 1][0], s[2 * kt + 1][1]);
            pa[3] = packhf(s[2 * kt + 1][2], s[2 * kt + 1][3]);
            #pragma unroll
            for (int dn = 0; dn < 4; dn++)
                mma16816h(o[dn], pa, bv[dn]);
        }

        if (t + 1 < NT) {
            const int nb = (t + 1) & 1;
            u32 so = srow * ROWU + scq * 4;
            *reinterpret_cast<uint4*>(&skk[nb][so]) = pk;
            *reinterpret_cast<uint4*>(&svv[nb][so]) = pv;
        }
        __syncthreads();
    }

    // ---- finalize: quad-reduce l, normalize, write ----------------------------
    {
        l0r += __shfl_xor_sync(0xffffffffu, l0r, 1);
        l0r += __shfl_xor_sync(0xffffffffu, l0r, 2);
        l1r += __shfl_xor_sync(0xffffffffu, l1r, 1);
        l1r += __shfl_xor_sync(0xffffffffu, l1r, 2);
        float inv0 = 1.0f / l0r;
        float inv1 = 1.0f / l1r;
        int r = bb * SEQ + sq0 + (lane >> 2);
        #pragma unroll
        for (int dn = 0; dn < 4; dn++) {
            int cc = h * HD + dn * 8 + 2 * (lane & 3);
            float2 o0 = {o[dn][0] * inv0, o[dn][1] * inv0};
            float2 o1 = {o[dn][2] * inv1, o[dn][3] * inv1};
            *reinterpret_cast<float2*>(xo + (size_t)r * CCH + cc)       = o0;
            *reinterpret_cast<float2*>(xo + (size_t)(r + 8) * CCH + cc) = o1;
        }
    }
}

// ---------------- [B*S, C] -> [B, C, S] output transpose -------------------
__global__ __launch_bounds__(256) void out_transpose_kernel(
    const float* __restrict__ src, float* __restrict__ dst)
{
    __shared__ float t[32][33];
    const int tx = threadIdx.x, ty = threadIdx.y;
    const int s0 = blockIdx.x * 32;
    const int c0 = blockIdx.y * 32;
    const int bb = blockIdx.z;
    #pragma unroll
    for (int i = ty; i < 32; i += 8)
        t[i][tx] = src[((size_t)bb * SEQ + s0 + i) * CCH + c0 + tx];
    __syncthreads();
    #pragma unroll
    for (int i = ty; i < 32; i += 8)
        dst[(size_t)bb * CCH * SEQ + (size_t)(c0 + i) * SEQ + s0 + tx] = t[tx][i];
}

// ---------------- launch ----------------------------------------------------
static float* symf(const void* symbol) {
    void* p = nullptr;
    cudaGetSymbolAddress(&p, symbol);
    return reinterpret_cast<float*>(p);
}
static u32* symu(const void* symbol) {
    void* p = nullptr;
    cudaGetSymbolAddress(&p, symbol);
    return reinterpret_cast<u32*>(p);
}

extern "C" void kernel_launch(void* const* d_in, const int* in_sizes, int n_in,
                              void* d_out, int out_size)
{
    const float* q = (const float*)d_in[0];
    const float* k = (const float*)d_in[1];
    const float* v = (const float*)d_in[2];
    const float* ln_g[3]  = {(const float*)d_in[3],  (const float*)d_in[9],  (const float*)d_in[15]};
    const float* ln_b[3]  = {(const float*)d_in[4],  (const float*)d_in[10], (const float*)d_in[16]};
    const float* w1[3]    = {(const float*)d_in[5],  (const float*)d_in[11], (const float*)d_in[17]};
    const float* b1[3]    = {(const float*)d_in[6],  (const float*)d_in[12], (const float*)d_in[18]};
    const float* w2[3]    = {(const float*)d_in[7],  (const float*)d_in[13], (const float*)d_in[19]};
    const float* b2[3]    = {(const float*)d_in[8],  (const float*)d_in[14], (const float*)d_in[20]};
    const float* m1_w1 = (const float*)d_in[21];
    const float* m1_b1 = (const float*)d_in[22];
    const float* m1_w2 = (const float*)d_in[23];
    const float* m1_b2 = (const float*)d_in[24];
    const float* m2_w1 = (const float*)d_in[25];
    const float* m2_b1 = (const float*)d_in[26];
    const float* m2_w2 = (const float*)d_in[27];
    const float* m2_b2 = (const float*)d_in[28];

    float* qp  = symf(g_qp);
    float* vp  = symf(g_vp);
    float* x   = symf(g_x);
    float* rs1 = symf(g_rs1);
    float* hb  = symf(g_h);
    float* x3  = symf(g_x3);
    float* h3  = symf(g_h3);
    u32* qf = symu(g_qf);
    u32* kf = symu(g_kf);
    u32* vf = symu(g_vf);

    const float qsc = 1.44269504088896f / 5.65685424949238f;  // log2e/sqrt(32)

    // ---- batched LN for q,k,v ----
    LNIn lp;
    lp.x[0] = q; lp.x[1] = k; lp.x[2] = v;
    for (int i = 0; i < 3; i++) { lp.g[i] = ln_g[i]; lp.b[i] = ln_b[i]; }
    ln_transpose_kernel<<<dim3(SEQ / 16, 2, 3), 256>>>(lp, x3);

    // ---- batched GEMM1 (C->2C, LeakyReLU) ----
    Ptrs3 W1 = {{w1[0], w1[1], w1[2]}};
    Ptrs3 B1 = {{b1[0], b1[1], b1[2]}};
    QKVOut dummy = {{nullptr, nullptr, nullptr}, {0.f, 0.f, 0.f}, nullptr};
    gemm_h1_kernel<true, false><<<dim3(HID / 64, NTOK / 128, 3), 128>>>(
        x3, (long)NTOK * CCH, W1, B1, h3, (long)NTOK * HID, dummy, CCH, HID);

    // ---- batched GEMM2 (2C->C, fp16 head-major out; v also fp32) ----
    Ptrs3 W2 = {{w2[0], w2[1], w2[2]}};
    Ptrs3 B2 = {{b2[0], b2[1], b2[2]}};
    QKVOut qo = {{qf, kf, vf}, {qsc, 1.f, 1.f}, vp};
    gemm_h1_kernel<false, true><<<dim3(CCH / 64, NTOK / 128, 3), 128>>>(
        h3, (long)NTOK * HID, W2, B2, nullptr, 0, qo, HID, CCH);

    // ---- attention (8 warps x 16 rows, unnormalized exp) ----
    attn_kernel<<<dim3(SEQ / 128, 2 * NH), 256>>>(x);

    // ---- MLPs (3-term split bf16, fp32-quality) ----
    dim3 g1(HID / 64, NTOK / 128);
    dim3 g2(CCH / 64, NTOK / 128);
    gemm_bf16_kernel<true,  false><<<g1, 128>>>(x,   m1_w1, m1_b1, nullptr, hb,  NTOK, CCH, HID);
    gemm_bf16_kernel<false, true ><<<g2, 128>>>(hb,  m1_w2, m1_b2, vp,      rs1, NTOK, HID, CCH);
    gemm_bf16_kernel<true,  false><<<g1, 128>>>(rs1, m2_w1, m2_b1, nullptr, hb,  NTOK, CCH, HID);
    gemm_bf16_kernel<false, true ><<<g2, 128>>>(hb,  m2_w2, m2_b2, rs1,     qp,  NTOK, HID, CCH);

    out_transpose_kernel<<<dim3(SEQ / 32, CCH / 32, 2), dim3(32, 8)>>>(qp, (float*)d_out);
}

// round 12
// speedup vs baseline: 1.4711x; 1.0407x over previous
#include <cuda_runtime.h>
#include <cuda_bf16.h>
#include <cstdint>

#define NTOK 8192      // B*S
#define CCH  128       // C
#define HID  256       // 2C
#define SEQ  4096      // S per batch
#define NH   4
#define HD   32

typedef unsigned int u32;

// ---------------- scratch (static device memory, no allocs) ----------------
__device__ float g_qp [NTOK * CCH];
__device__ float g_vp [NTOK * CCH];
__device__ float g_x  [NTOK * CCH];
__device__ float g_rs1[NTOK * CCH];
__device__ float g_h  [NTOK * HID];
__device__ float g_x3 [3 * NTOK * CCH];
__device__ float g_h3 [3 * NTOK * HID];
// head-major fp16 operands: [b*NH+h][token][16 u32]
__device__ u32 g_qf[2 * NH * SEQ * 16];
__device__ u32 g_kf[2 * NH * SEQ * 16];
__device__ u32 g_vf[2 * NH * SEQ * 16];

struct Ptrs3  { const float* p[3]; };
struct LNIn   { const float* x[3]; const float* g[3]; const float* b[3]; };
struct QKVOut { u32* o16[3]; float sc[3]; float* vC; };

// ---------------- pack helpers ----------------------------------------------
__device__ __forceinline__ u32 packhf(float x, float y) {      // fp16x2, x->low
    u32 d; asm("cvt.rn.f16x2.f32 %0,%2,%1;" : "=r"(d) : "f"(x), "f"(y)); return d;
}
__device__ __forceinline__ float exf(float x) {                // MUFU exp2
    float r; asm("ex2.approx.f32 %0,%1;" : "=f"(r) : "f"(x)); return r;
}
__device__ __forceinline__ u32 sptr(const void* p) {
    u32 a; asm("{.reg .u64 t; cvta.to.shared.u64 t,%1; cvt.u32.u64 %0,t;}" : "=r"(a) : "l"(p));
    return a;
}

// ---------------- mma / ldmatrix wrappers -----------------------------------
__device__ __forceinline__ void mma16816h(float* c, const u32* a, const u32* b) { // fp16
    asm volatile(
        "mma.sync.aligned.m16n8k16.row.col.f32.f16.f16.f32 "
        "{%0,%1,%2,%3},{%4,%5,%6,%7},{%8,%9},{%0,%1,%2,%3};"
        : "+f"(c[0]), "+f"(c[1]), "+f"(c[2]), "+f"(c[3])
        : "r"(a[0]), "r"(a[1]), "r"(a[2]), "r"(a[3]), "r"(b[0]), "r"(b[1]));
}
__device__ __forceinline__ void ldsm4(u32& r0, u32& r1, u32& r2, u32& r3, u32 addr) {
    asm volatile("ldmatrix.sync.aligned.m8n8.x4.shared.b16 {%0,%1,%2,%3},[%4];"
                 : "=r"(r0), "=r"(r1), "=r"(r2), "=r"(r3) : "r"(addr));
}
__device__ __forceinline__ void ldsm4t(u32& r0, u32& r1, u32& r2, u32& r3, u32 addr) {
    asm volatile("ldmatrix.sync.aligned.m8n8.x4.trans.shared.b16 {%0,%1,%2,%3},[%4];"
                 : "=r"(r0), "=r"(r1), "=r"(r2), "=r"(r3) : "r"(addr));
}

// ---------------- LayerNorm + transpose, batched over q/k/v ------------------
__global__ __launch_bounds__(256) void ln_transpose_kernel(LNIn in, float* __restrict__ y3)
{
    __shared__ float tile[CCH][17];
    const int z   = blockIdx.z;
    const float* x   = in.x[z];
    const float* gam = in.g[z];
    const float* bet = in.b[z];
    float* y = y3 + (size_t)z * NTOK * CCH;

    const int tid = threadIdx.x;
    const int s0  = blockIdx.x * 16;
    const int bb  = blockIdx.y;

    #pragma unroll
    for (int it = 0; it < 8; it++) {
        int idx = tid + it * 256;
        int c = idx >> 4, t = idx & 15;
        tile[c][t] = x[(size_t)bb * CCH * SEQ + (size_t)c * SEQ + s0 + t];
    }
    __syncthreads();

    const int w = tid >> 5, lane = tid & 31;
    #pragma unroll
    for (int rep = 0; rep < 2; rep++) {
        int t = w * 2 + rep;
        float sum = 0.f, sq = 0.f;
        #pragma unroll
        for (int j = 0; j < 4; j++) {
            float v = tile[lane + 32 * j][t];
            sum += v; sq += v * v;
        }
        #pragma unroll
        for (int off = 16; off > 0; off >>= 1) {
            sum += __shfl_xor_sync(0xffffffffu, sum, off);
            sq  += __shfl_xor_sync(0xffffffffu, sq,  off);
        }
        float mu   = sum * (1.0f / CCH);
        float var  = sq * (1.0f / CCH) - mu * mu;
        float rstd = rsqrtf(var + 1e-5f);
        size_t row = ((size_t)bb * SEQ + s0 + t) * CCH;
        #pragma unroll
        for (int j = 0; j < 4; j++) {
            int c = lane + 32 * j;
            y[row + c] = (tile[c][t] - mu) * rstd * gam[c] + bet[c];
        }
    }
}

#define AROW 12
#define BROW 36

// ---------------- single-term fp16 GEMM, batched over z (q/k/v) --------------
template <bool LEAKY, bool QKV>
__global__ __launch_bounds__(128, 2) void gemm_h1_kernel(
    const float* __restrict__ Abase, long Astride,
    Ptrs3 W, Ptrs3 Bi,
    float* __restrict__ Cbase, long Cstride,
    QKVOut qo, int K, int M)
{
    __shared__ __align__(16) u32 sA[2][128 * AROW];
    __shared__ __align__(16) u32 sB[2][16 * BROW];

    const int z = blockIdx.z;
    const float* A    = Abase + (size_t)z * Astride;
    const float* Bw   = W.p[z];
    const float* bias = Bi.p[z];

    const int tid  = threadIdx.x;
    const int lane = tid & 31;
    const int w    = tid >> 5;
    const int n0 = blockIdx.y * 128;
    const int m0 = blockIdx.x * 64;

    const int g  = lane >> 3;
    const int lr = lane & 7;

    int arow[4], acol[4];
    #pragma unroll
    for (int j = 0; j < 4; j++) {
        int idx = tid + 128 * j;
        arow[j] = idx >> 2;
        acol[j] = idx & 3;
    }
    int brow[2], bcol[2];
    #pragma unroll
    for (int j = 0; j < 2; j++) {
        int idx = tid + 128 * j;
        brow[j] = idx >> 4;
        bcol[j] = idx & 15;
    }

    float c[2][8][4];
    #pragma unroll
    for (int mi = 0; mi < 2; mi++)
        #pragma unroll
        for (int nt = 0; nt < 8; nt++)
            #pragma unroll
            for (int e = 0; e < 4; e++) c[mi][nt][e] = 0.f;

    const u32 bA0 = sptr(&sA[0][0]);
    const u32 bB0 = sptr(&sB[0][0]);
    const u32 abuf = 128 * AROW * 4;
    const u32 bbuf = 16 * BROW * 4;

    const int NT = K >> 4;

    float4 af[4], bf4[2];
    #pragma unroll
    for (int j = 0; j < 4; j++)
        af[j] = *reinterpret_cast<const float4*>(&A[(size_t)(n0 + arow[j]) * K + acol[j] * 4]);
    #pragma unroll
    for (int j = 0; j < 2; j++)
        bf4[j] = *reinterpret_cast<const float4*>(&Bw[(size_t)brow[j] * M + m0 + bcol[j] * 4]);

    #pragma unroll
    for (int j = 0; j < 4; j++) {
        int o = arow[j] * AROW + acol[j] * 2;
        sA[0][o]     = packhf(af[j].x, af[j].y);
        sA[0][o + 1] = packhf(af[j].z, af[j].w);
    }
    #pragma unroll
    for (int j = 0; j < 2; j++) {
        int o = brow[j] * BROW + bcol[j] * 2;
        sB[0][o]     = packhf(bf4[j].x, bf4[j].y);
        sB[0][o + 1] = packhf(bf4[j].z, bf4[j].w);
    }
    __syncthreads();

    for (int t = 0; t < NT; t++) {
        const int buf = t & 1;
        const u32 aS = bA0 + buf * abuf;
        const u32 bS = bB0 + buf * bbuf;

        if (t + 1 < NT) {
            int k0 = (t + 1) * 16;
            #pragma unroll
            for (int j = 0; j < 4; j++)
                af[j] = *reinterpret_cast<const float4*>(&A[(size_t)(n0 + arow[j]) * K + k0 + acol[j] * 4]);
            #pragma unroll
            for (int j = 0; j < 2; j++)
                bf4[j] = *reinterpret_cast<const float4*>(&Bw[(size_t)(k0 + brow[j]) * M + m0 + bcol[j] * 4]);
        }

        u32 aF[2][4];
        #pragma unroll
        for (int mi = 0; mi < 2; mi++) {
            u32 off = (u32)((w * 32 + mi * 16 + (g & 1) * 8 + lr) * 48 + (g >> 1) * 16);
            ldsm4(aF[mi][0], aF[mi][1], aF[mi][2], aF[mi][3], aS + off);
        }
        u32 bF[8][2];
        #pragma unroll
        for (int dp = 0; dp < 4; dp++) {
            u32 off = (u32)((8 * (g & 1) + lr) * 144 + (dp * 16 + 8 * (g >> 1)) * 2);
            ldsm4t(bF[2 * dp][0], bF[2 * dp][1], bF[2 * dp + 1][0], bF[2 * dp + 1][1], bS + off);
        }

        #pragma unroll
        for (int mi = 0; mi < 2; mi++)
            #pragma unroll
            for (int nt = 0; nt < 8; nt++)
                mma16816h(c[mi][nt], aF[mi], bF[nt]);

        if (t + 1 < NT) {
            const int nb = (t + 1) & 1;
            #pragma unroll
            for (int j = 0; j < 4; j++) {
                int o = arow[j] * AROW + acol[j] * 2;
                sA[nb][o]     = packhf(af[j].x, af[j].y);
                sA[nb][o + 1] = packhf(af[j].z, af[j].w);
            }
            #pragma unroll
            for (int j = 0; j < 2; j++) {
                int o = brow[j] * BROW + bcol[j] * 2;
                sB[nb][o]     = packhf(bf4[j].x, bf4[j].y);
                sB[nb][o + 1] = packhf(bf4[j].z, bf4[j].w);
            }
        }
        __syncthreads();
    }

    // ---- epilogue -----------------------------------------------------------
    #pragma unroll
    for (int mi = 0; mi < 2; mi++) {
        int r0 = n0 + w * 32 + mi * 16 + (lane >> 2);
        #pragma unroll
        for (int nt = 0; nt < 8; nt++) {
            int col = m0 + nt * 8 + (lane & 3) * 2;
            float2 bb = *reinterpret_cast<const float2*>(&bias[col]);
            float v0 = c[mi][nt][0] + bb.x;
            float v1 = c[mi][nt][1] + bb.y;
            float v2 = c[mi][nt][2] + bb.x;
            float v3 = c[mi][nt][3] + bb.y;
            if (LEAKY) {
                v0 = fmaxf(v0, 0.f) + 0.01f * fminf(v0, 0.f);
                v1 = fmaxf(v1, 0.f) + 0.01f * fminf(v1, 0.f);
                v2 = fmaxf(v2, 0.f) + 0.01f * fminf(v2, 0.f);
                v3 = fmaxf(v3, 0.f) + 0.01f * fminf(v3, 0.f);
            }
            if (!QKV) {
                float* C = Cbase + (size_t)z * Cstride;
                *reinterpret_cast<float2*>(&C[(size_t)r0 * M + col])       = make_float2(v0, v1);
                *reinterpret_cast<float2*>(&C[(size_t)(r0 + 8) * M + col]) = make_float2(v2, v3);
            } else {
                int h = col >> 5, dpair = (col & 31) >> 1;
                int bI = r0 >> 12, sI = r0 & (SEQ - 1);
                size_t oA = ((size_t)(bI * NH + h) * SEQ + sI) * 16 + dpair;
                size_t oB = oA + 8 * 16;
                u32* o16 = qo.o16[z];
                float sc = qo.sc[z];
                o16[oA] = packhf(v0 * sc, v1 * sc);
                o16[oB] = packhf(v2 * sc, v3 * sc);
                if (z == 2) {
                    *reinterpret_cast<float2*>(&qo.vC[(size_t)r0 * M + col])       = make_float2(v0, v1);
                    *reinterpret_cast<float2*>(&qo.vC[(size_t)(r0 + 8) * M + col]) = make_float2(v2, v3);
                }
            }
        }
    }
}

// ---------------- single-term fp16 GEMM (MLP path, LEAKY/RES) ----------------
template <bool LEAKY, bool RES>
__global__ __launch_bounds__(128, 2) void gemm_f16s_kernel(
    const float* __restrict__ A, const float* __restrict__ Bw,
    const float* __restrict__ bias, const float* __restrict__ res,
    float* __restrict__ C, int K, int M)
{
    __shared__ __align__(16) u32 sA[2][128 * AROW];
    __shared__ __align__(16) u32 sB[2][16 * BROW];

    const int tid  = threadIdx.x;
    const int lane = tid & 31;
    const int w    = tid >> 5;
    const int n0 = blockIdx.y * 128;
    const int m0 = blockIdx.x * 64;

    const int g  = lane >> 3;
    const int lr = lane & 7;

    int arow[4], acol[4];
    #pragma unroll
    for (int j = 0; j < 4; j++) {
        int idx = tid + 128 * j;
        arow[j] = idx >> 2;
        acol[j] = idx & 3;
    }
    int brow[2], bcol[2];
    #pragma unroll
    for (int j = 0; j < 2; j++) {
        int idx = tid + 128 * j;
        brow[j] = idx >> 4;
        bcol[j] = idx & 15;
    }

    float c[2][8][4];
    #pragma unroll
    for (int mi = 0; mi < 2; mi++)
        #pragma unroll
        for (int nt = 0; nt < 8; nt++)
            #pragma unroll
            for (int e = 0; e < 4; e++) c[mi][nt][e] = 0.f;

    const u32 bA0 = sptr(&sA[0][0]);
    const u32 bB0 = sptr(&sB[0][0]);
    const u32 abuf = 128 * AROW * 4;
    const u32 bbuf = 16 * BROW * 4;

    const int NT = K >> 4;

    float4 af[4], bf4[2];
    #pragma unroll
    for (int j = 0; j < 4; j++)
        af[j] = *reinterpret_cast<const float4*>(&A[(size_t)(n0 + arow[j]) * K + acol[j] * 4]);
    #pragma unroll
    for (int j = 0; j < 2; j++)
        bf4[j] = *reinterpret_cast<const float4*>(&Bw[(size_t)brow[j] * M + m0 + bcol[j] * 4]);

    #pragma unroll
    for (int j = 0; j < 4; j++) {
        int o = arow[j] * AROW + acol[j] * 2;
        sA[0][o]     = packhf(af[j].x, af[j].y);
        sA[0][o + 1] = packhf(af[j].z, af[j].w);
    }
    #pragma unroll
    for (int j = 0; j < 2; j++) {
        int o = brow[j] * BROW + bcol[j] * 2;
        sB[0][o]     = packhf(bf4[j].x, bf4[j].y);
        sB[0][o + 1] = packhf(bf4[j].z, bf4[j].w);
    }
    __syncthreads();

    for (int t = 0; t < NT; t++) {
        const int buf = t & 1;
        const u32 aS = bA0 + buf * abuf;
        const u32 bS = bB0 + buf * bbuf;

        if (t + 1 < NT) {
            int k0 = (t + 1) * 16;
            #pragma unroll
            for (int j = 0; j < 4; j++)
                af[j] = *reinterpret_cast<const float4*>(&A[(size_t)(n0 + arow[j]) * K + k0 + acol[j] * 4]);
            #pragma unroll
            for (int j = 0; j < 2; j++)
                bf4[j] = *reinterpret_cast<const float4*>(&Bw[(size_t)(k0 + brow[j]) * M + m0 + bcol[j] * 4]);
        }

        u32 aF[2][4];
        #pragma unroll
        for (int mi = 0; mi < 2; mi++) {
            u32 off = (u32)((w * 32 + mi * 16 + (g & 1) * 8 + lr) * 48 + (g >> 1) * 16);
            ldsm4(aF[mi][0], aF[mi][1], aF[mi][2], aF[mi][3], aS + off);
        }
        u32 bF[8][2];
        #pragma unroll
        for (int dp = 0; dp < 4; dp++) {
            u32 off = (u32)((8 * (g & 1) + lr) * 144 + (dp * 16 + 8 * (g >> 1)) * 2);
            ldsm4t(bF[2 * dp][0], bF[2 * dp][1], bF[2 * dp + 1][0], bF[2 * dp + 1][1], bS + off);
        }

        #pragma unroll
        for (int mi = 0; mi < 2; mi++)
            #pragma unroll
            for (int nt = 0; nt < 8; nt++)
                mma16816h(c[mi][nt], aF[mi], bF[nt]);

        if (t + 1 < NT) {
            const int nb = (t + 1) & 1;
            #pragma unroll
            for (int j = 0; j < 4; j++) {
                int o = arow[j] * AROW + acol[j] * 2;
                sA[nb][o]     = packhf(af[j].x, af[j].y);
                sA[nb][o + 1] = packhf(af[j].z, af[j].w);
            }
            #pragma unroll
            for (int j = 0; j < 2; j++) {
                int o = brow[j] * BROW + bcol[j] * 2;
                sB[nb][o]     = packhf(bf4[j].x, bf4[j].y);
                sB[nb][o + 1] = packhf(bf4[j].z, bf4[j].w);
            }
        }
        __syncthreads();
    }

    #pragma unroll
    for (int mi = 0; mi < 2; mi++) {
        int r0 = n0 + w * 32 + mi * 16 + (lane >> 2);
        #pragma unroll
        for (int nt = 0; nt < 8; nt++) {
            int col = m0 + nt * 8 + (lane & 3) * 2;
            float2 bb = *reinterpret_cast<const float2*>(&bias[col]);
            float v0 = c[mi][nt][0] + bb.x;
            float v1 = c[mi][nt][1] + bb.y;
            float v2 = c[mi][nt][2] + bb.x;
            float v3 = c[mi][nt][3] + bb.y;
            if (LEAKY) {
                v0 = fmaxf(v0, 0.f) + 0.01f * fminf(v0, 0.f);
                v1 = fmaxf(v1, 0.f) + 0.01f * fminf(v1, 0.f);
                v2 = fmaxf(v2, 0.f) + 0.01f * fminf(v2, 0.f);
                v3 = fmaxf(v3, 0.f) + 0.01f * fminf(v3, 0.f);
            }
            if (RES) {
                float2 r4a = *reinterpret_cast<const float2*>(&res[(size_t)r0 * M + col]);
                float2 r4b = *reinterpret_cast<const float2*>(&res[(size_t)(r0 + 8) * M + col]);
                v0 += r4a.x; v1 += r4a.y; v2 += r4b.x; v3 += r4b.y;
            }
            *reinterpret_cast<float2*>(&C[(size_t)r0 * M + col])       = make_float2(v0, v1);
            *reinterpret_cast<float2*>(&C[(size_t)(r0 + 8) * M + col]) = make_float2(v2, v3);
        }
    }
}

// ---------------- FA attention: unnormalized exp2, hoisted LDS addrs ---------
#define KVT 64
#define ROWU 20

__global__ __launch_bounds__(256, 2) void attn_kernel(float* __restrict__ xo)
{
    __shared__ __align__(16) u32 skk[2][KVT * ROWU];
    __shared__ __align__(16) u32 svv[2][KVT * ROWU];

    const int tid  = threadIdx.x;
    const int lane = tid & 31;
    const int w    = tid >> 5;                 // 0..7
    const int bh   = blockIdx.y;
    const int bb   = bh >> 2, h = bh & 3;
    const int sq0  = blockIdx.x * 128 + w * 16;

    // ---- load Q fragments (fp16, pre-scaled) --------------------------------
    u32 qR[2][4];
    {
        size_t qb = ((size_t)bh * SEQ + sq0 + (lane >> 2)) * 16;
        #pragma unroll
        for (int kt = 0; kt < 2; kt++) {
            int d0 = kt * 8 + (lane & 3);
            qR[kt][0] = g_qf[qb + d0];
            qR[kt][1] = g_qf[qb + 8 * 16 + d0];
            qR[kt][2] = g_qf[qb + d0 + 4];
            qR[kt][3] = g_qf[qb + 8 * 16 + d0 + 4];
        }
    }

    float o[4][4];
    #pragma unroll
    for (int dn = 0; dn < 4; dn++)
        #pragma unroll
        for (int e = 0; e < 4; e++) o[dn][e] = 0.f;
    float l0r = 0.f, l1r = 0.f;

    const int srow = tid >> 2;
    const int scq  = tid & 3;
    const size_t kvbase = (size_t)bh * SEQ * 16;

    const int g  = lane >> 3;
    const int lr = lane & 7;
    const u32 bK0 = sptr(&skk[0][0]);
    const u32 bV0 = sptr(&svv[0][0]);
    const u32 bufstride = KVT * ROWU * 4;
    const u32 ssoff = (u32)(srow * ROWU + scq * 4);

    // hoisted ldmatrix offsets (loop-invariant, lane-derived)
    u32 koff[2][4], voff[4][2];
    #pragma unroll
    for (int kt = 0; kt < 2; kt++)
        #pragma unroll
        for (int ap = 0; ap < 4; ap++)
            koff[kt][ap] = (u32)((16 * ap + 8 * (g >> 1) + lr) * 80 + (kt * 16 + 8 * (g & 1)) * 2);
    #pragma unroll
    for (int kt = 0; kt < 4; kt++)
        #pragma unroll
        for (int dp = 0; dp < 2; dp++)
            voff[kt][dp] = (u32)((16 * kt + 8 * (g & 1) + lr) * 80 + (dp * 16 + 8 * (g >> 1)) * 2);

    uint4 pk, pv;
    {
        size_t go = kvbase + (size_t)srow * 16 + scq * 4;
        pk = *reinterpret_cast<const uint4*>(g_kf + go);
        pv = *reinterpret_cast<const uint4*>(g_vf + go);
    }
    *reinterpret_cast<uint4*>(&skk[0][ssoff]) = pk;
    *reinterpret_cast<uint4*>(&svv[0][ssoff]) = pv;
    __syncthreads();

    const int NT = SEQ / KVT;
    for (int t = 0; t < NT; t++) {
        const int buf = t & 1;
        const u32 bK = bK0 + buf * bufstride;
        const u32 bV = bV0 + buf * bufstride;

        if (t + 1 < NT) {
            size_t go = kvbase + (size_t)((t + 1) * KVT + srow) * 16 + scq * 4;
            pk = *reinterpret_cast<const uint4*>(g_kf + go);
            pv = *reinterpret_cast<const uint4*>(g_vf + go);
        }

        // ---- QK^T : S[16 x 64] per warp ------------------------------------
        float s[8][4];
        #pragma unroll
        for (int nt = 0; nt < 8; nt++)
            #pragma unroll
            for (int e = 0; e < 4; e++) s[nt][e] = 0.f;

        #pragma unroll
        for (int kt = 0; kt < 2; kt++) {
            u32 bk_[8][2];
            #pragma unroll
            for (int ap = 0; ap < 4; ap++)
                ldsm4(bk_[2 * ap][0], bk_[2 * ap][1], bk_[2 * ap + 1][0], bk_[2 * ap + 1][1],
                      bK + koff[kt][ap]);
            #pragma unroll
            for (int nt = 0; nt < 8; nt++)
                mma16816h(s[nt], qR[kt], bk_[nt]);
        }

        // ---- unnormalized exp ------------------------------------------------
        #pragma unroll
        for (int nt = 0; nt < 8; nt++) {
            float p0 = exf(s[nt][0]);
            float p1 = exf(s[nt][1]);
            float p2 = exf(s[nt][2]);
            float p3 = exf(s[nt][3]);
            s[nt][0] = p0; s[nt][1] = p1;
            s[nt][2] = p2; s[nt][3] = p3;
            l0r += p0 + p1;
            l1r += p2 + p3;
        }

        // ---- P @ V -----------------------------------------------------------
        #pragma unroll
        for (int kt = 0; kt < 4; kt++) {
            u32 bv[4][2];
            #pragma unroll
            for (int dp = 0; dp < 2; dp++)
                ldsm4t(bv[2 * dp][0], bv[2 * dp][1], bv[2 * dp + 1][0], bv[2 * dp + 1][1],
                       bV + voff[kt][dp]);
            u32 pa[4];
            pa[0] = packhf(s[2 * kt][0],     s[2 * kt][1]);
            pa[1] = packhf(s[2 * kt][2],     s[2 * kt][3]);
            pa[2] = packhf(s[2 * kt + 1][0], s[2 * kt + 1][1]);
            pa[3] = packhf(s[2 * kt + 1][2], s[2 * kt + 1][3]);
            #pragma unroll
            for (int dn = 0; dn < 4; dn++)
                mma16816h(o[dn], pa, bv[dn]);
        }

        if (t + 1 < NT) {
            const int nb = (t + 1) & 1;
            *reinterpret_cast<uint4*>(&skk[nb][ssoff]) = pk;
            *reinterpret_cast<uint4*>(&svv[nb][ssoff]) = pv;
        }
        __syncthreads();
    }

    // ---- finalize: quad-reduce l, normalize, write ----------------------------
    {
        l0r += __shfl_xor_sync(0xffffffffu, l0r, 1);
        l0r += __shfl_xor_sync(0xffffffffu, l0r, 2);
        l1r += __shfl_xor_sync(0xffffffffu, l1r, 1);
        l1r += __shfl_xor_sync(0xffffffffu, l1r, 2);
        float inv0 = 1.0f / l0r;
        float inv1 = 1.0f / l1r;
        int r = bb * SEQ + sq0 + (lane >> 2);
        #pragma unroll
        for (int dn = 0; dn < 4; dn++) {
            int cc = h * HD + dn * 8 + 2 * (lane & 3);
            float2 o0 = {o[dn][0] * inv0, o[dn][1] * inv0};
            float2 o1 = {o[dn][2] * inv1, o[dn][3] * inv1};
            *reinterpret_cast<float2*>(xo + (size_t)r * CCH + cc)       = o0;
            *reinterpret_cast<float2*>(xo + (size_t)(r + 8) * CCH + cc) = o1;
        }
    }
}

// ---------------- [B*S, C] -> [B, C, S] output transpose -------------------
__global__ __launch_bounds__(256) void out_transpose_kernel(
    const float* __restrict__ src, float* __restrict__ dst)
{
    __shared__ float t[32][33];
    const int tx = threadIdx.x, ty = threadIdx.y;
    const int s0 = blockIdx.x * 32;
    const int c0 = blockIdx.y * 32;
    const int bb = blockIdx.z;
    #pragma unroll
    for (int i = ty; i < 32; i += 8)
        t[i][tx] = src[((size_t)bb * SEQ + s0 + i) * CCH + c0 + tx];
    __syncthreads();
    #pragma unroll
    for (int i = ty; i < 32; i += 8)
        dst[(size_t)bb * CCH * SEQ + (size_t)(c0 + i) * SEQ + s0 + tx] = t[tx][i];
}

// ---------------- launch ----------------------------------------------------
static float* symf(const void* symbol) {
    void* p = nullptr;
    cudaGetSymbolAddress(&p, symbol);
    return reinterpret_cast<float*>(p);
}
static u32* symu(const void* symbol) {
    void* p = nullptr;
    cudaGetSymbolAddress(&p, symbol);
    return reinterpret_cast<u32*>(p);
}

extern "C" void kernel_launch(void* const* d_in, const int* in_sizes, int n_in,
                              void* d_out, int out_size)
{
    const float* q = (const float*)d_in[0];
    const float* k = (const float*)d_in[1];
    const float* v = (const float*)d_in[2];
    const float* ln_g[3]  = {(const float*)d_in[3],  (const float*)d_in[9],  (const float*)d_in[15]};
    const float* ln_b[3]  = {(const float*)d_in[4],  (const float*)d_in[10], (const float*)d_in[16]};
    const float* w1[3]    = {(const float*)d_in[5],  (const float*)d_in[11], (const float*)d_in[17]};
    const float* b1[3]    = {(const float*)d_in[6],  (const float*)d_in[12], (const float*)d_in[18]};
    const float* w2[3]    = {(const float*)d_in[7],  (const float*)d_in[13], (const float*)d_in[19]};
    const float* b2[3]    = {(const float*)d_in[8],  (const float*)d_in[14], (const float*)d_in[20]};
    const float* m1_w1 = (const float*)d_in[21];
    const float* m1_b1 = (const float*)d_in[22];
    const float* m1_w2 = (const float*)d_in[23];
    const float* m1_b2 = (const float*)d_in[24];
    const float* m2_w1 = (const float*)d_in[25];
    const float* m2_b1 = (const float*)d_in[26];
    const float* m2_w2 = (const float*)d_in[27];
    const float* m2_b2 = (const float*)d_in[28];

    float* qp  = symf(g_qp);
    float* vp  = symf(g_vp);
    float* x   = symf(g_x);
    float* rs1 = symf(g_rs1);
    float* hb  = symf(g_h);
    float* x3  = symf(g_x3);
    float* h3  = symf(g_h3);
    u32* qf = symu(g_qf);
    u32* kf = symu(g_kf);
    u32* vf = symu(g_vf);

    const float qsc = 1.44269504088896f / 5.65685424949238f;  // log2e/sqrt(32)

    // ---- batched LN for q,k,v ----
    LNIn lp;
    lp.x[0] = q; lp.x[1] = k; lp.x[2] = v;
    for (int i = 0; i < 3; i++) { lp.g[i] = ln_g[i]; lp.b[i] = ln_b[i]; }
    ln_transpose_kernel<<<dim3(SEQ / 16, 2, 3), 256>>>(lp, x3);

    // ---- batched GEMM1 (C->2C, LeakyReLU) ----
    Ptrs3 W1 = {{w1[0], w1[1], w1[2]}};
    Ptrs3 B1 = {{b1[0], b1[1], b1[2]}};
    QKVOut dummy = {{nullptr, nullptr, nullptr}, {0.f, 0.f, 0.f}, nullptr};
    gemm_h1_kernel<true, false><<<dim3(HID / 64, NTOK / 128, 3), 128>>>(
        x3, (long)NTOK * CCH, W1, B1, h3, (long)NTOK * HID, dummy, CCH, HID);

    // ---- batched GEMM2 (2C->C, fp16 head-major out; v also fp32) ----
    Ptrs3 W2 = {{w2[0], w2[1], w2[2]}};
    Ptrs3 B2 = {{b2[0], b2[1], b2[2]}};
    QKVOut qo = {{qf, kf, vf}, {qsc, 1.f, 1.f}, vp};
    gemm_h1_kernel<false, true><<<dim3(CCH / 64, NTOK / 128, 3), 128>>>(
        h3, (long)NTOK * HID, W2, B2, nullptr, 0, qo, HID, CCH);

    // ---- attention ----
    attn_kernel<<<dim3(SEQ / 128, 2 * NH), 256>>>(x);

    // ---- MLPs (single-term fp16) ----
    dim3 g1(HID / 64, NTOK / 128);
    dim3 g2(CCH / 64, NTOK / 128);
    gemm_f16s_kernel<true,  false><<<g1, 128>>>(x,   m1_w1, m1_b1, nullptr, hb,  CCH, HID);
    gemm_f16s_kernel<false, true ><<<g2, 128>>>(hb,  m1_w2, m1_b2, vp,      rs1, HID, CCH);
    gemm_f16s_kernel<true,  false><<<g1, 128>>>(rs1, m2_w1, m2_b1, nullptr, hb,  CCH, HID);
    gemm_f16s_kernel<false, true ><<<g2, 128>>>(hb,  m2_w2, m2_b2, rs1,     qp,  HID, CCH);

    out_transpose_kernel<<<dim3(SEQ / 32, CCH / 32, 2), dim3(32, 8)>>>(qp, (float*)d_out);
}